// round 8
// baseline (speedup 1.0000x reference)
#include <cuda_runtime.h>
#include <math.h>

#define BATCH 4
#define SEQ_M 1024
#define HDIM  1024
#define NHEAD 8
#define DHEAD 128
#define SEQ_L 1024
#define NEXP  8
#define FDIM  4096
#define NTOK  (BATCH*SEQ_M)     /* 4096 tokens */
#define NBH   (BATCH*NHEAD)     /* 32 */
#define LT    (SEQ_L+SEQ_M)     /* 2048 */
#define NSLOT (NTOK*2)          /* 8192 (token, expert) slots */

// ---------------- scratch (device globals; no allocations allowed) ----------
__device__ float g_q[(size_t)NBH*SEQ_M*DHEAD];
__device__ float g_k[(size_t)NBH*LT*DHEAD];
__device__ float g_v[(size_t)NBH*LT*DHEAD];
__device__ float g_s[(size_t)NBH*SEQ_M*SEQ_L];
__device__ float g_ao[(size_t)NTOK*HDIM];             // tf32-rounded at write
__device__ float g_t1[(size_t)NTOK*HDIM];
__device__ float g_h1[(size_t)NTOK*HDIM];             // fp32 (gate/combine)
__device__ float g_h1t[(size_t)NTOK*HDIM];            // tf32-rounded copy
__device__ float g_hidden[(size_t)NSLOT*FDIM];        // tf32-rounded at write
__device__ float g_y[(size_t)NSLOT*HDIM];
__device__ float g_hallt[(size_t)BATCH*LT*HDIM];      // tf32 concat(h_cache,h)
__device__ float g_wqt[(size_t)HDIM*HDIM];
__device__ float g_wkt[(size_t)HDIM*HDIM];
__device__ float g_wvt[(size_t)HDIM*HDIM];
__device__ float g_wot[(size_t)HDIM*HDIM];
__device__ float g_w1t[(size_t)NEXP*HDIM*FDIM];
__device__ float g_w2t[(size_t)NEXP*FDIM*HDIM];
__device__ int   g_cnt[NEXP];
__device__ int   g_cur[NEXP];
__device__ int   g_off[NEXP];
__device__ int   g_slot_token[NSLOT];
__device__ float g_slot_w[NSLOT];
__device__ int   g_token_slot[NTOK*2];
__device__ int   g_top_e[NTOK*2];
__device__ float g_top_w[NTOK*2];

// ---------------- tf32 helpers -----------------------------------------------
__device__ __forceinline__ unsigned f2tf(float x)
{
    unsigned y;
    asm("cvt.rna.tf32.f32 %0, %1;" : "=r"(y) : "f"(x));
    return y;
}
__device__ __forceinline__ float4 tf4(float4 v)
{
    return make_float4(__uint_as_float(f2tf(v.x)), __uint_as_float(f2tf(v.y)),
                       __uint_as_float(f2tf(v.z)), __uint_as_float(f2tf(v.w)));
}
__device__ __forceinline__ unsigned sm_u32(const void* p)
{
    return (unsigned)__cvta_generic_to_shared((void*)p);
}

#define MMA_TF32(d0,d1,d2,d3,a0,a1,a2,a3,b0,b1)                             \
    asm volatile("mma.sync.aligned.m16n8k8.row.col.f32.tf32.tf32.f32 "      \
        "{%0,%1,%2,%3}, {%4,%5,%6,%7}, {%8,%9}, {%0,%1,%2,%3};"             \
        : "+f"(d0),"+f"(d1),"+f"(d2),"+f"(d3)                               \
        : "r"(a0),"r"(a1),"r"(a2),"r"(a3),"r"(b0),"r"(b1));

#define CP_ASYNC16(smaddr, gptr)                                            \
    asm volatile("cp.async.cg.shared.global [%0], [%1], 16;"                \
                 :: "r"(smaddr), "l"(gptr))
#define CP_COMMIT() asm volatile("cp.async.commit_group;")
#define CP_WAIT2()  asm volatile("cp.async.wait_group 2;")

// ---------------- cp.async tf32 GEMM (128x128x16, 4-stage pipeline) -----------
// 256 threads = 8 warps (4x2); warp tile 32(M) x 64(N).
// A smem: [stage][128 m][20]  (stride 20 -> fragment LDS conflict-free)
// B smem: [stage][16 k][136]  (stride 136 -> conflict-free)
// Dynamic smem = 4*(128*20 + 16*136)*4 = 75776 bytes.
#define GEMM_SMEM_BYTES (4*(128*20 + 16*136)*4)

#define GEMM_DECLS                                                           \
    const int tid = threadIdx.x, lane = tid & 31, warp = tid >> 5;           \
    const int wm = warp >> 1, wn = warp & 1;                                 \
    const int fg = lane >> 2, fc = lane & 3;                                 \
    const int alm = tid & 127, alk = (tid >> 7) * 8;                         \
    const int bro = tid >> 4, bco = (tid & 15) * 8;                          \
    extern __shared__ float smem[];                                          \
    float* smA = smem;                                                       \
    float* smB = smem + 4*128*20;                                            \
    const unsigned smAu = sm_u32(smA), smBu = sm_u32(smB);

#define CP_STAGE(s, kb, LDB) {                                               \
    unsigned _a = smAu + (unsigned)(((s)*2560 + alm*20 + alk)*4);            \
    const float* _as = a_row + (size_t)(kb)*16 + alk;                        \
    CP_ASYNC16(_a, _as); CP_ASYNC16(_a+16, _as+4);                           \
    unsigned _b = smBu + (unsigned)(((s)*2176 + bro*136 + bco)*4);           \
    const float* _bs = b_ptr + (size_t)((kb)*16 + bro)*(LDB) + bco;          \
    CP_ASYNC16(_b, _bs); CP_ASYNC16(_b+16, _bs+4); }

#define GEMM_COMPUTE(sAp, sBp) {                                             \
    unsigned af[2][4], bf[8][2];                                             \
    _Pragma("unroll") for (int k8 = 0; k8 < 16; k8 += 8) {                   \
      _Pragma("unroll") for (int mt = 0; mt < 2; mt++) {                     \
        const int mr = wm*32 + mt*16 + fg;                                   \
        af[mt][0] = __float_as_uint((sAp)[mr*20 + k8+fc]);                   \
        af[mt][1] = __float_as_uint((sAp)[(mr+8)*20 + k8+fc]);               \
        af[mt][2] = __float_as_uint((sAp)[mr*20 + k8+fc+4]);                 \
        af[mt][3] = __float_as_uint((sAp)[(mr+8)*20 + k8+fc+4]); }           \
      _Pragma("unroll") for (int nt = 0; nt < 8; nt++) {                     \
        const int nc = wn*64 + nt*8 + fg;                                    \
        bf[nt][0] = __float_as_uint((sBp)[(k8+fc)*136 + nc]);                \
        bf[nt][1] = __float_as_uint((sBp)[(k8+fc+4)*136 + nc]); }            \
      _Pragma("unroll") for (int mt = 0; mt < 2; mt++)                       \
      _Pragma("unroll") for (int nt = 0; nt < 8; nt++)                       \
        MMA_TF32(acc[mt][nt][0],acc[mt][nt][1],acc[mt][nt][2],               \
                 acc[mt][nt][3],af[mt][0],af[mt][1],af[mt][2],af[mt][3],     \
                 bf[nt][0],bf[nt][1]); } }

#define GEMM_MAIN(NKB, LDB)                                                  \
    _Pragma("unroll") for (int s = 0; s < 3; s++) {                          \
        CP_STAGE(s, s, LDB); CP_COMMIT(); }                                  \
    float acc[2][8][4] = {};                                                 \
    for (int kb = 0; kb < (NKB); kb++) {                                     \
        CP_WAIT2();                                                          \
        __syncthreads();                                                     \
        if (kb + 3 < (NKB)) CP_STAGE((kb+3)&3, kb+3, LDB);                   \
        CP_COMMIT();                                                         \
        const float* sAp = smA + (kb&3)*2560;                                \
        const float* sBp = smB + (kb&3)*2176;                                \
        GEMM_COMPUTE(sAp, sBp)                                               \
    }

// ---------------- block reductions (256 threads / 8 warps) --------------------
__device__ __forceinline__ float blk_sum8(float v, float* sbuf)
{
    const int lane = threadIdx.x & 31, w = threadIdx.x >> 5;
#pragma unroll
    for (int o = 16; o; o >>= 1) v += __shfl_xor_sync(0xffffffffu, v, o);
    __syncthreads();
    if (lane == 0) sbuf[w] = v;
    __syncthreads();
    return sbuf[0]+sbuf[1]+sbuf[2]+sbuf[3]+sbuf[4]+sbuf[5]+sbuf[6]+sbuf[7];
}

__device__ __forceinline__ float blk_max8(float v, float* sbuf)
{
    const int lane = threadIdx.x & 31, w = threadIdx.x >> 5;
#pragma unroll
    for (int o = 16; o; o >>= 1) v = fmaxf(v, __shfl_xor_sync(0xffffffffu, v, o));
    __syncthreads();
    if (lane == 0) sbuf[w] = v;
    __syncthreads();
    return fmaxf(fmaxf(fmaxf(sbuf[0],sbuf[1]),fmaxf(sbuf[2],sbuf[3])),
                 fmaxf(fmaxf(sbuf[4],sbuf[5]),fmaxf(sbuf[6],sbuf[7])));
}

// ---------------- init + tf32 prepass ------------------------------------------
__global__ void k_init()
{
    int t = threadIdx.x;
    if (t < NEXP) { g_cnt[t] = 0; g_cur[t] = 0; }
}

__device__ __forceinline__ float* round_dst(int d)
{
    switch (d) {
        case 0: return g_wqt;
        case 1: return g_wkt;
        case 2: return g_wvt;
        case 3: return g_wot;
        case 4: return g_w1t;
        default: return g_w2t;
    }
}

__global__ void __launch_bounds__(256) k_round(const float* __restrict__ src, int d)
{
    float* dst = round_dst(d);
    const size_t i = ((size_t)blockIdx.x * 256 + threadIdx.x) * 4;
    *(float4*)(dst + i) = tf4(*(const float4*)(src + i));
}

__global__ void __launch_bounds__(256) k_round_hall(const float* __restrict__ h,
                                                    const float* __restrict__ hc)
{
    const size_t i = ((size_t)blockIdx.x * 256 + threadIdx.x) * 4;
    const int col = (int)(i & (HDIM - 1));
    const int r = (int)(i >> 10);
    const int b = r >> 11, t = r & 2047;
    const float* src = (t < SEQ_L)
        ? hc + ((size_t)(b * SEQ_L + t)) * HDIM + col
        : h  + ((size_t)(b * SEQ_M + (t - SEQ_L))) * HDIM + col;
    *(float4*)(g_hallt + i) = tf4(*(const float4*)src);
}

// ---------------- QKV projections (cp.async tf32 GEMM) ---------------------------
template<int WHICH>
__global__ void __launch_bounds__(256, 2) k_proj()
{
    GEMM_DECLS
    const int m0 = blockIdx.y * 128, n0 = blockIdx.x * 128;

    const int arow = m0 + alm;
    const float* a_row;
    if (WHICH == 0) {
        const int b = arow >> 10, mm = arow & 1023;
        a_row = g_hallt + ((size_t)(b * LT + SEQ_L + mm)) * HDIM;
    } else {
        a_row = g_hallt + (size_t)arow * HDIM;
    }
    const float* b_ptr = ((WHICH == 0) ? g_wqt : (WHICH == 1) ? g_wkt : g_wvt) + n0;

    GEMM_MAIN(HDIM/16, HDIM)

#pragma unroll
    for (int mt = 0; mt < 2; mt++) {
        const int r0 = m0 + wm*32 + mt*16 + fg;
        const int r1 = r0 + 8;
#pragma unroll
        for (int nt = 0; nt < 8; nt++) {
            const int col = n0 + wn*64 + nt*8 + fc*2;
            const int nh = col >> 7, d = col & 127;
            float *o0, *o1;
            if (WHICH == 0) {
                int b = r0 >> 10, mm = r0 & 1023;
                o0 = g_q + (((size_t)(b*NHEAD + nh) * SEQ_M + mm) * DHEAD + d);
                b = r1 >> 10; mm = r1 & 1023;
                o1 = g_q + (((size_t)(b*NHEAD + nh) * SEQ_M + mm) * DHEAD + d);
            } else {
                float* base = (WHICH == 1) ? g_k : g_v;
                int b = r0 >> 11, t = r0 & 2047;
                o0 = base + (((size_t)(b*NHEAD + nh) * LT + t) * DHEAD + d);
                b = r1 >> 11; t = r1 & 2047;
                o1 = base + (((size_t)(b*NHEAD + nh) * LT + t) * DHEAD + d);
            }
            *(float2*)o0 = make_float2(acc[mt][nt][0], acc[mt][nt][1]);
            *(float2*)o1 = make_float2(acc[mt][nt][2], acc[mt][nt][3]);
        }
    }
}

// ---------------- banded scores (fp32) --------------------------------------------
__global__ void __launch_bounds__(256) k_scores(const float* __restrict__ pos)
{
    __shared__ float Qs[16][64];
    __shared__ float Ks[16][128];
    __shared__ float Ps[16][64];
    const int bh = blockIdx.z;
    const int i0 = blockIdx.y * 64, j0 = blockIdx.x * 64;
    const int tid = threadIdx.x, ty = tid >> 4, tx = tid & 15;

    const float* qbase = g_q + (size_t)bh * SEQ_M * DHEAD;
    const float* kbase = g_k + (size_t)bh * LT * DHEAD;

    const int qi = tid >> 2, qk = (tid & 3) * 4;
    const int kr = tid >> 1, kk8 = (tid & 1) * 8;
    const int pk = tid >> 4, pj = (tid & 15) * 4;

    float acc[4][4] = {};
    for (int dc = 0; dc < DHEAD; dc += 16) {
        float4 qv = *(const float4*)(qbase + (size_t)(i0 + qi) * DHEAD + dc + qk);
        Qs[qk+0][qi] = qv.x; Qs[qk+1][qi] = qv.y;
        Qs[qk+2][qi] = qv.z; Qs[qk+3][qi] = qv.w;
        float4 k0 = *(const float4*)(kbase + (size_t)(i0 + j0 + kr) * DHEAD + dc + kk8);
        float4 k1 = *(const float4*)(kbase + (size_t)(i0 + j0 + kr) * DHEAD + dc + kk8 + 4);
        Ks[kk8+0][kr] = k0.x; Ks[kk8+1][kr] = k0.y; Ks[kk8+2][kr] = k0.z; Ks[kk8+3][kr] = k0.w;
        Ks[kk8+4][kr] = k1.x; Ks[kk8+5][kr] = k1.y; Ks[kk8+6][kr] = k1.z; Ks[kk8+7][kr] = k1.w;
        *(float4*)&Ps[pk][pj] = *(const float4*)(pos + (size_t)(dc + pk) * SEQ_L + j0 + pj);
        __syncthreads();
#pragma unroll
        for (int kk = 0; kk < 16; kk++) {
            float4 q4 = *(const float4*)&Qs[kk][ty*4];
            float4 p4 = *(const float4*)&Ps[kk][tx*4];
            const int base = (ty + tx) * 4;
            float4 ka = *(const float4*)&Ks[kk][base];
            float4 kb2 = *(const float4*)&Ks[kk][base + 4];
            float qr[4] = {q4.x,q4.y,q4.z,q4.w};
            float pr[4] = {p4.x,p4.y,p4.z,p4.w};
            float kv[8] = {ka.x,ka.y,ka.z,ka.w,kb2.x,kb2.y,kb2.z,kb2.w};
#pragma unroll
            for (int i = 0; i < 4; i++)
#pragma unroll
                for (int j = 0; j < 4; j++)
                    acc[i][j] = fmaf(qr[i], kv[i+j] + pr[j], acc[i][j]);
        }
        __syncthreads();
    }
    const float scale = 1.0f / 32.0f;
#pragma unroll
    for (int i = 0; i < 4; i++) {
        const int row = i0 + ty*4 + i;
        *(float4*)(g_s + ((size_t)bh * SEQ_M + row) * SEQ_L + j0 + tx*4) =
            make_float4(acc[i][0]*scale, acc[i][1]*scale, acc[i][2]*scale, acc[i][3]*scale);
    }
}

// ---------------- softmax ----------------------------------------------------------
__global__ void __launch_bounds__(256) k_softmax()
{
    __shared__ float sbuf[8];
    const size_t row = blockIdx.x;
    float* p = g_s + row * SEQ_L;
    const int c0 = threadIdx.x * 4;
    float4 v = *(const float4*)(p + c0);
    float mx = fmaxf(fmaxf(v.x, v.y), fmaxf(v.z, v.w));
    mx = blk_max8(mx, sbuf);
    float e0 = __expf(v.x - mx), e1 = __expf(v.y - mx);
    float e2 = __expf(v.z - mx), e3 = __expf(v.w - mx);
    float s = blk_sum8(e0 + e1 + e2 + e3, sbuf);
    const float inv = 1.0f / s;
    *(float4*)(p + c0) = make_float4(e0*inv, e1*inv, e2*inv, e3*inv);
}

// ---------------- banded AV (fp32, output rounded to tf32) --------------------------
__global__ void __launch_bounds__(256) k_av()
{
    __shared__ float As[16][64];
    __shared__ float Vs[16][64];
    const int bh = blockIdx.z;
    const int i0 = blockIdx.y * 64;
    const int d0 = blockIdx.x * 64;
    const int tid = threadIdx.x, ty = tid >> 4, tx = tid & 15;

    const float* abase = g_s + (size_t)bh * SEQ_M * SEQ_L;
    const float* vbase = g_v + (size_t)bh * LT * DHEAD;

    const int ail = tid >> 2;
    const int ar4 = (tid & 3) * 4;
    const float* arow_ptr = abase + (size_t)(i0 + ail) * SEQ_L;
    const int vr = tid >> 4, vd4 = (tid & 15) * 4;

    float acc[4][4] = {};
    for (int ch = 0; ch < (64 + SEQ_L) / 16; ch++) {
        const int ch16 = ch * 16;
        const int r0c = i0 + ch16;
#pragma unroll
        for (int u = 0; u < 4; u++) {
            const int rr = ar4 + u;
            const int j = ch16 + rr - ail;
            As[rr][ail] = (j >= 0 && j < SEQ_L) ? arow_ptr[j] : 0.0f;
        }
        *(float4*)&Vs[vr][vd4] =
            *(const float4*)(vbase + (size_t)(r0c + vr) * DHEAD + d0 + vd4);
        __syncthreads();
#pragma unroll
        for (int rr = 0; rr < 16; rr++) {
            float4 a4 = *(const float4*)&As[rr][ty*4];
            float4 v4 = *(const float4*)&Vs[rr][tx*4];
            float ar[4] = {a4.x,a4.y,a4.z,a4.w};
            float vv[4] = {v4.x,v4.y,v4.z,v4.w};
#pragma unroll
            for (int i = 0; i < 4; i++)
#pragma unroll
                for (int j = 0; j < 4; j++)
                    acc[i][j] = fmaf(ar[i], vv[j], acc[i][j]);
        }
        __syncthreads();
    }
    const int b = bh >> 3, nh = bh & 7;
#pragma unroll
    for (int i = 0; i < 4; i++) {
        const int row = i0 + ty*4 + i;
        *(float4*)(g_ao + ((size_t)(b * SEQ_M + row)) * HDIM + nh * DHEAD + d0 + tx*4) =
            tf4(make_float4(acc[i][0], acc[i][1], acc[i][2], acc[i][3]));
    }
}

// ---------------- Wo projection + residual (cp.async tf32 GEMM) --------------------
__global__ void __launch_bounds__(256, 2) k_wo(const float* __restrict__ h)
{
    GEMM_DECLS
    const int m0 = blockIdx.y * 128, n0 = blockIdx.x * 128;

    const float* a_row = g_ao + (size_t)(m0 + alm) * HDIM;
    const float* b_ptr = g_wot + n0;

    GEMM_MAIN(HDIM/16, HDIM)

#pragma unroll
    for (int mt = 0; mt < 2; mt++) {
        const int r0 = m0 + wm*32 + mt*16 + fg;
        const int r1 = r0 + 8;
#pragma unroll
        for (int nt = 0; nt < 8; nt++) {
            const int col = n0 + wn*64 + nt*8 + fc*2;
            float2 h0 = *(const float2*)(h + (size_t)r0 * HDIM + col);
            float2 h1 = *(const float2*)(h + (size_t)r1 * HDIM + col);
            *(float2*)(g_t1 + (size_t)r0 * HDIM + col) =
                make_float2(acc[mt][nt][0] + h0.x, acc[mt][nt][1] + h0.y);
            *(float2*)(g_t1 + (size_t)r1 * HDIM + col) =
                make_float2(acc[mt][nt][2] + h1.x, acc[mt][nt][3] + h1.y);
        }
    }
}

// ---------------- LN1 (writes fp32 g_h1 + tf32 g_h1t) --------------------------------
__global__ void __launch_bounds__(256) k_ln1(const float* __restrict__ g,
                                             const float* __restrict__ b)
{
    __shared__ float sbuf[8];
    const int row = blockIdx.x;
    const int c0 = threadIdx.x * 4;
    float4 xv = *(const float4*)(g_t1 + (size_t)row * HDIM + c0);
    float s  = xv.x + xv.y + xv.z + xv.w;
    float s2 = xv.x*xv.x + xv.y*xv.y + xv.z*xv.z + xv.w*xv.w;
    s  = blk_sum8(s,  sbuf);
    s2 = blk_sum8(s2, sbuf);
    const float mu = s * (1.0f / HDIM);
    const float var = s2 * (1.0f / HDIM) - mu * mu;
    const float inv = rsqrtf(var + 1e-5f);
    float4 gv = *(const float4*)(g + c0);
    float4 bv = *(const float4*)(b + c0);
    float4 r = make_float4(
        (xv.x - mu) * inv * gv.x + bv.x,
        (xv.y - mu) * inv * gv.y + bv.y,
        (xv.z - mu) * inv * gv.z + bv.z,
        (xv.w - mu) * inv * gv.w + bv.w);
    *(float4*)(g_h1  + (size_t)row * HDIM + c0) = r;
    *(float4*)(g_h1t + (size_t)row * HDIM + c0) = tf4(r);
}

// ---------------- gating --------------------------------------------------------------
__global__ void __launch_bounds__(256) k_gate(const float* __restrict__ gw,
                                              const float* __restrict__ gb)
{
    __shared__ float lg[NEXP];
    const int t = blockIdx.x;
    const float* x = g_h1 + (size_t)t * HDIM;
    const int tid = threadIdx.x, w = tid >> 5, lane = tid & 31;
    float s = 0.0f;
    for (int hh = lane; hh < HDIM; hh += 32)
        s = fmaf(x[hh], gw[hh * NEXP + w], s);
#pragma unroll
    for (int o = 16; o; o >>= 1) s += __shfl_xor_sync(0xffffffffu, s, o);
    if (lane == 0) lg[w] = s + gb[w];
    __syncthreads();
    if (tid == 0) {
        int i0 = 0;
        for (int e = 1; e < NEXP; e++) if (lg[e] > lg[i0]) i0 = e;
        int i1 = -1;
        for (int e = 0; e < NEXP; e++) {
            if (e == i0) continue;
            if (i1 < 0 || lg[e] > lg[i1]) i1 = e;
        }
        const float e1 = __expf(lg[i1] - lg[i0]);
        const float den = 1.0f / (1.0f + e1);
        g_top_e[2*t]   = i0; g_top_e[2*t+1] = i1;
        g_top_w[2*t]   = den;
        g_top_w[2*t+1] = e1 * den;
        atomicAdd(&g_cnt[i0], 1);
        atomicAdd(&g_cnt[i1], 1);
    }
}

__global__ void k_scan()
{
    int s = 0;
    for (int e = 0; e < NEXP; e++) { g_off[e] = s; s += g_cnt[e]; }
}

__global__ void __launch_bounds__(256) k_scatter()
{
    const int t = blockIdx.x * 256 + threadIdx.x;
    if (t >= NTOK) return;
#pragma unroll
    for (int k = 0; k < 2; k++) {
        const int e = g_top_e[2*t + k];
        const int p = atomicAdd(&g_cur[e], 1);
        const int pos = g_off[e] + p;
        g_slot_token[pos] = t;
        g_slot_w[pos] = g_top_w[2*t + k];
        g_token_slot[2*t + k] = pos;
    }
}

// ---------------- MoE GEMM1 (cp.async tf32 GEMM) ----------------------------------------
__global__ void __launch_bounds__(256, 2) k_moe1(const float* __restrict__ b1)
{
    const int e = blockIdx.z;
    const int cnt = g_cnt[e];
    const int r0b = blockIdx.y * 128;
    if (r0b >= cnt) return;
    const int off = g_off[e];

    __shared__ int toks[128];
    GEMM_DECLS
    const int n0 = blockIdx.x * 128;

    if (tid < 128) {
        const int r = r0b + tid;
        toks[tid] = (r < cnt) ? g_slot_token[off + r] : -1;
    }
    __syncthreads();
    const int tok = toks[alm];
    const float* a_row = g_h1t + (size_t)(tok >= 0 ? tok : 0) * HDIM;
    const float* b_ptr = g_w1t + (size_t)e * HDIM * FDIM + n0;

    GEMM_MAIN(HDIM/16, FDIM)

#pragma unroll
    for (int mt = 0; mt < 2; mt++) {
        const int r0 = r0b + wm*32 + mt*16 + fg;
        const int r1 = r0 + 8;
#pragma unroll
        for (int nt = 0; nt < 8; nt++) {
            const int col = n0 + wn*64 + nt*8 + fc*2;
            float2 bb = *(const float2*)(b1 + (size_t)e * FDIM + col);
            if (r0 < cnt) {
                float2 r = make_float2(fmaxf(acc[mt][nt][0] + bb.x, 0.f),
                                       fmaxf(acc[mt][nt][1] + bb.y, 0.f));
                r.x = __uint_as_float(f2tf(r.x)); r.y = __uint_as_float(f2tf(r.y));
                *(float2*)(g_hidden + (size_t)(off + r0) * FDIM + col) = r;
            }
            if (r1 < cnt) {
                float2 r = make_float2(fmaxf(acc[mt][nt][2] + bb.x, 0.f),
                                       fmaxf(acc[mt][nt][3] + bb.y, 0.f));
                r.x = __uint_as_float(f2tf(r.x)); r.y = __uint_as_float(f2tf(r.y));
                *(float2*)(g_hidden + (size_t)(off + r1) * FDIM + col) = r;
            }
        }
    }
}

// ---------------- MoE GEMM2 (cp.async tf32 GEMM) ------------------------------------------
__global__ void __launch_bounds__(256, 2) k_moe2(const float* __restrict__ b2)
{
    const int e = blockIdx.z;
    const int cnt = g_cnt[e];
    const int r0b = blockIdx.y * 128;
    if (r0b >= cnt) return;
    const int off = g_off[e];

    GEMM_DECLS
    const int n0 = blockIdx.x * 128;

    const int r = r0b + alm;
    const float* a_row = g_hidden + (size_t)(off + (r < cnt ? r : 0)) * FDIM;
    const float* b_ptr = g_w2t + (size_t)e * FDIM * HDIM + n0;

    GEMM_MAIN(FDIM/16, HDIM)

#pragma unroll
    for (int mt = 0; mt < 2; mt++) {
        const int r0 = r0b + wm*32 + mt*16 + fg;
        const int r1 = r0 + 8;
#pragma unroll
        for (int nt = 0; nt < 8; nt++) {
            const int col = n0 + wn*64 + nt*8 + fc*2;
            float2 bb = *(const float2*)(b2 + (size_t)e * HDIM + col);
            if (r0 < cnt)
                *(float2*)(g_y + (size_t)(off + r0) * HDIM + col) =
                    make_float2(acc[mt][nt][0] + bb.x, acc[mt][nt][1] + bb.y);
            if (r1 < cnt)
                *(float2*)(g_y + (size_t)(off + r1) * HDIM + col) =
                    make_float2(acc[mt][nt][2] + bb.x, acc[mt][nt][3] + bb.y);
        }
    }
}

// ---------------- combine + LN2 -----------------------------------------------------------
__global__ void __launch_bounds__(256) k_combine(const float* __restrict__ mom_in,
                                                 const float* __restrict__ g,
                                                 const float* __restrict__ b,
                                                 float* __restrict__ out)
{
    __shared__ float sbuf[8];
    const int t = blockIdx.x;
    const int s0 = g_token_slot[2*t], s1 = g_token_slot[2*t + 1];
    const float w0 = g_slot_w[s0], w1 = g_slot_w[s1];
    const int c0 = threadIdx.x * 4;

    float4 h1v = *(const float4*)(g_h1 + (size_t)t * HDIM + c0);
    float4 mv  = *(const float4*)(mom_in + (size_t)t * HDIM + c0);
    float4 y0  = *(const float4*)(g_y + (size_t)s0 * HDIM + c0);
    float4 y1  = *(const float4*)(g_y + (size_t)s1 * HDIM + c0);

    float momn[4], x[4];
    momn[0] = 0.7f*mv.x + w0*y0.x + w1*y1.x;
    momn[1] = 0.7f*mv.y + w0*y0.y + w1*y1.y;
    momn[2] = 0.7f*mv.z + w0*y0.z + w1*y1.z;
    momn[3] = 0.7f*mv.w + w0*y0.w + w1*y1.w;
    x[0] = h1v.x - momn[0]; x[1] = h1v.y - momn[1];
    x[2] = h1v.z - momn[2]; x[3] = h1v.w - momn[3];

    float s  = x[0] + x[1] + x[2] + x[3];
    float s2 = x[0]*x[0] + x[1]*x[1] + x[2]*x[2] + x[3]*x[3];
    s  = blk_sum8(s,  sbuf);
    s2 = blk_sum8(s2, sbuf);
    const float mu = s * (1.0f / HDIM);
    const float var = s2 * (1.0f / HDIM) - mu * mu;
    const float inv = rsqrtf(var + 1e-5f);
    float4 gv = *(const float4*)(g + c0);
    float4 bv = *(const float4*)(b + c0);

    *(float4*)(out + (size_t)t * HDIM + c0) = make_float4(
        (x[0] - mu) * inv * gv.x + bv.x,
        (x[1] - mu) * inv * gv.y + bv.y,
        (x[2] - mu) * inv * gv.z + bv.z,
        (x[3] - mu) * inv * gv.w + bv.w);
    *(float4*)(out + (size_t)NTOK * HDIM + (size_t)t * HDIM + c0) =
        make_float4(momn[0], momn[1], momn[2], momn[3]);
}

// ---------------- launch ---------------------------------------------------------------------
extern "C" void kernel_launch(void* const* d_in, const int* in_sizes, int n_in,
                              void* d_out, int out_size)
{
    const float* h       = (const float*)d_in[0];
    const float* h_cache = (const float*)d_in[1];
    const float* pos     = (const float*)d_in[2];
    const float* mom     = (const float*)d_in[3];
    const float* Wq      = (const float*)d_in[4];
    const float* Wk      = (const float*)d_in[5];
    const float* Wv      = (const float*)d_in[6];
    const float* Wo      = (const float*)d_in[7];
    const float* gate_w  = (const float*)d_in[8];
    const float* gate_b  = (const float*)d_in[9];
    const float* w1      = (const float*)d_in[10];
    const float* b1      = (const float*)d_in[11];
    const float* w2      = (const float*)d_in[12];
    const float* b2      = (const float*)d_in[13];
    const float* ln1g    = (const float*)d_in[14];
    const float* ln1b    = (const float*)d_in[15];
    const float* ln2g    = (const float*)d_in[16];
    const float* ln2b    = (const float*)d_in[17];
    float* out = (float*)d_out;

    cudaFuncSetAttribute(k_proj<0>, cudaFuncAttributeMaxDynamicSharedMemorySize, GEMM_SMEM_BYTES);
    cudaFuncSetAttribute(k_proj<1>, cudaFuncAttributeMaxDynamicSharedMemorySize, GEMM_SMEM_BYTES);
    cudaFuncSetAttribute(k_proj<2>, cudaFuncAttributeMaxDynamicSharedMemorySize, GEMM_SMEM_BYTES);
    cudaFuncSetAttribute(k_wo,      cudaFuncAttributeMaxDynamicSharedMemorySize, GEMM_SMEM_BYTES);
    cudaFuncSetAttribute(k_moe1,    cudaFuncAttributeMaxDynamicSharedMemorySize, GEMM_SMEM_BYTES);
    cudaFuncSetAttribute(k_moe2,    cudaFuncAttributeMaxDynamicSharedMemorySize, GEMM_SMEM_BYTES);

    k_init<<<1, 32>>>();
    // tf32 prepass
    k_round<<<(HDIM*HDIM)/1024, 256>>>(Wq, 0);
    k_round<<<(HDIM*HDIM)/1024, 256>>>(Wk, 1);
    k_round<<<(HDIM*HDIM)/1024, 256>>>(Wv, 2);
    k_round<<<(HDIM*HDIM)/1024, 256>>>(Wo, 3);
    k_round<<<(NEXP*HDIM*FDIM)/1024, 256>>>(w1, 4);
    k_round<<<(NEXP*FDIM*HDIM)/1024, 256>>>(w2, 5);
    k_round_hall<<<(BATCH*LT*HDIM)/1024, 256>>>(h, h_cache);

    k_proj<0><<<dim3(HDIM/128, NTOK/128), 256, GEMM_SMEM_BYTES>>>();
    k_proj<1><<<dim3(HDIM/128, (BATCH*LT)/128), 256, GEMM_SMEM_BYTES>>>();
    k_proj<2><<<dim3(HDIM/128, (BATCH*LT)/128), 256, GEMM_SMEM_BYTES>>>();
    k_scores<<<dim3(SEQ_L/64, SEQ_M/64, NBH), 256>>>(pos);
    k_softmax<<<NBH*SEQ_M, 256>>>();
    k_av<<<dim3(DHEAD/64, SEQ_M/64, NBH), 256>>>();
    k_wo<<<dim3(HDIM/128, NTOK/128), 256, GEMM_SMEM_BYTES>>>(h);
    k_ln1<<<NTOK, 256>>>(ln1g, ln1b);
    k_gate<<<NTOK, 256>>>(gate_w, gate_b);
    k_scan<<<1, 1>>>();
    k_scatter<<<NTOK/256, 256>>>();
    k_moe1<<<dim3(FDIM/128, NSLOT/128, NEXP), 256, GEMM_SMEM_BYTES>>>(b1);
    k_moe2<<<dim3(HDIM/128, NSLOT/128, NEXP), 256, GEMM_SMEM_BYTES>>>(b2);
    k_combine<<<NTOK, 256>>>(mom, ln2g, ln2b, out);
}

// round 9
// speedup vs baseline: 1.1874x; 1.1874x over previous
#include <cuda_runtime.h>
#include <math.h>

#define BATCH 4
#define SEQ_M 1024
#define HDIM  1024
#define NHEAD 8
#define DHEAD 128
#define SEQ_L 1024
#define NEXP  8
#define FDIM  4096
#define NTOK  (BATCH*SEQ_M)     /* 4096 tokens */
#define NBH   (BATCH*NHEAD)     /* 32 */
#define LT    (SEQ_L+SEQ_M)     /* 2048 */
#define NSLOT (NTOK*2)          /* 8192 (token, expert) slots */

// ---------------- scratch (device globals; no allocations allowed) ----------
__device__ float g_q[(size_t)NBH*SEQ_M*DHEAD];
__device__ float g_k[(size_t)NBH*LT*DHEAD];
__device__ float g_v[(size_t)NBH*LT*DHEAD];
__device__ float g_s[(size_t)NBH*SEQ_M*SEQ_L];
__device__ float g_ao[(size_t)NTOK*HDIM];
__device__ float g_t1[(size_t)NTOK*HDIM];
__device__ float g_h1[(size_t)NTOK*HDIM];
__device__ float g_hidden[(size_t)NSLOT*FDIM];
__device__ float g_y[(size_t)NSLOT*HDIM];
__device__ int   g_cnt[NEXP];
__device__ int   g_cur[NEXP];
__device__ int   g_off[NEXP];
__device__ int   g_slot_token[NSLOT];
__device__ float g_slot_w[NSLOT];
__device__ int   g_token_slot[NTOK*2];
__device__ int   g_top_e[NTOK*2];
__device__ float g_top_w[NTOK*2];

// ---------------- tf32 helpers -----------------------------------------------
__device__ __forceinline__ unsigned f2tf(float x)
{
    unsigned y;
    asm("cvt.rna.tf32.f32 %0, %1;" : "=r"(y) : "f"(x));
    return y;
}
__device__ __forceinline__ float4 tf4(float4 v)
{
    return make_float4(__uint_as_float(f2tf(v.x)), __uint_as_float(f2tf(v.y)),
                       __uint_as_float(f2tf(v.z)), __uint_as_float(f2tf(v.w)));
}

#define MMA_TF32(d0,d1,d2,d3,a0,a1,a2,a3,b0,b1)                             \
    asm volatile("mma.sync.aligned.m16n8k8.row.col.f32.tf32.tf32.f32 "      \
        "{%0,%1,%2,%3}, {%4,%5,%6,%7}, {%8,%9}, {%0,%1,%2,%3};"             \
        : "+f"(d0),"+f"(d1),"+f"(d2),"+f"(d3)                               \
        : "r"(a0),"r"(a1),"r"(a2),"r"(a3),"r"(b0),"r"(b1));

// ---------------- tf32 128x64x16 GEMM building blocks -------------------------
// 256 threads = 8 warps (4x2); warp tile 32(M) x 32(N); mma m16n8k8.
// A smem [buf][k16][136] (transposed store, conflict-free), B smem [buf][k16][72].
// acc = 32 regs -> 3 CTAs/SM (24 warps) for latency hiding.
#define TF32_DECLS                                                           \
    const int tid = threadIdx.x, lane = tid & 31, warp = tid >> 5;           \
    const int wm = warp >> 1, wn = warp & 1;                                 \
    const int fg = lane >> 2, fc = lane & 3;                                 \
    const int alm = tid & 127, alk = (tid >> 7) * 8;                         \
    const int blkr = tid >> 4, bln = (tid & 15) * 4;

#define TF32_STORE(buf, PA0, PA1, PB0)                                       \
    { const float* _p0 = (const float*)&(PA0);                              \
      const float* _p1 = (const float*)&(PA1);                              \
      _Pragma("unroll")                                                      \
      for (int i = 0; i < 4; i++) {                                          \
          As[buf][alk+i][alm]   = __uint_as_float(f2tf(_p0[i]));             \
          As[buf][alk+4+i][alm] = __uint_as_float(f2tf(_p1[i]));             \
      }                                                                      \
      *(float4*)&Bs[buf][blkr][bln] = tf4(PB0); }

#define TF32_COMPUTE(cur)                                                    \
    _Pragma("unroll")                                                        \
    for (int k8 = 0; k8 < 16; k8 += 8) {                                     \
        unsigned afr[2][4], bfr[4][2];                                       \
        _Pragma("unroll")                                                    \
        for (int mt = 0; mt < 2; mt++) {                                     \
            const int mr = wm*32 + mt*16 + fg;                               \
            afr[mt][0] = __float_as_uint(As[cur][k8+fc  ][mr]);              \
            afr[mt][1] = __float_as_uint(As[cur][k8+fc  ][mr+8]);            \
            afr[mt][2] = __float_as_uint(As[cur][k8+fc+4][mr]);              \
            afr[mt][3] = __float_as_uint(As[cur][k8+fc+4][mr+8]);            \
        }                                                                    \
        _Pragma("unroll")                                                    \
        for (int nt = 0; nt < 4; nt++) {                                     \
            const int nc = wn*32 + nt*8 + fg;                                \
            bfr[nt][0] = __float_as_uint(Bs[cur][k8+fc  ][nc]);              \
            bfr[nt][1] = __float_as_uint(Bs[cur][k8+fc+4][nc]);              \
        }                                                                    \
        _Pragma("unroll")                                                    \
        for (int mt = 0; mt < 2; mt++)                                       \
        _Pragma("unroll")                                                    \
        for (int nt = 0; nt < 4; nt++)                                       \
            MMA_TF32(acc[mt][nt][0],acc[mt][nt][1],acc[mt][nt][2],           \
                     acc[mt][nt][3],                                         \
                     afr[mt][0],afr[mt][1],afr[mt][2],afr[mt][3],            \
                     bfr[nt][0],bfr[nt][1]);                                 \
    }

// ---------------- block reductions (256 threads / 8 warps) --------------------
__device__ __forceinline__ float blk_sum8(float v, float* sbuf)
{
    const int lane = threadIdx.x & 31, w = threadIdx.x >> 5;
#pragma unroll
    for (int o = 16; o; o >>= 1) v += __shfl_xor_sync(0xffffffffu, v, o);
    __syncthreads();
    if (lane == 0) sbuf[w] = v;
    __syncthreads();
    return sbuf[0]+sbuf[1]+sbuf[2]+sbuf[3]+sbuf[4]+sbuf[5]+sbuf[6]+sbuf[7];
}

__device__ __forceinline__ float blk_max8(float v, float* sbuf)
{
    const int lane = threadIdx.x & 31, w = threadIdx.x >> 5;
#pragma unroll
    for (int o = 16; o; o >>= 1) v = fmaxf(v, __shfl_xor_sync(0xffffffffu, v, o));
    __syncthreads();
    if (lane == 0) sbuf[w] = v;
    __syncthreads();
    return fmaxf(fmaxf(fmaxf(sbuf[0],sbuf[1]),fmaxf(sbuf[2],sbuf[3])),
                 fmaxf(fmaxf(sbuf[4],sbuf[5]),fmaxf(sbuf[6],sbuf[7])));
}

// ---------------- init ----------------------------------------------------------
__global__ void k_init()
{
    int t = threadIdx.x;
    if (t < NEXP) { g_cnt[t] = 0; g_cur[t] = 0; }
}

// ---------------- QKV projections (tf32 tensor) ---------------------------------
template<int WHICH>
__global__ void __launch_bounds__(256, 3) k_proj(
    const float* __restrict__ h, const float* __restrict__ h_cache,
    const float* __restrict__ W)
{
    __shared__ float As[2][16][136];
    __shared__ float Bs[2][16][72];
    TF32_DECLS
    const int m0 = blockIdx.y * 128, n0 = blockIdx.x * 64;

    const int arow = m0 + alm;
    const float* aptr;
    if (WHICH == 0) {
        aptr = h + (size_t)arow * HDIM;
    } else {
        const int b = arow >> 11, t = arow & 2047;
        aptr = (t < SEQ_L) ? (h_cache + ((size_t)b * SEQ_L + t) * HDIM)
                           : (h + ((size_t)b * SEQ_M + (t - SEQ_L)) * HDIM);
    }
    const float* bptr = W + (size_t)blkr * HDIM + n0 + bln;

    float4 pa0 = *(const float4*)(aptr + alk);
    float4 pa1 = *(const float4*)(aptr + alk + 4);
    float4 pb0 = *(const float4*)(bptr);
    TF32_STORE(0, pa0, pa1, pb0)
    __syncthreads();

    float acc[2][4][4] = {};
    const int NKB = HDIM / 16;
    for (int kb = 0; kb < NKB; kb++) {
        const int cur = kb & 1;
        if (kb + 1 < NKB) {
            pa0 = *(const float4*)(aptr + (kb+1)*16 + alk);
            pa1 = *(const float4*)(aptr + (kb+1)*16 + alk + 4);
            pb0 = *(const float4*)(bptr + (size_t)(kb+1)*16 * HDIM);
        }
        TF32_COMPUTE(cur)
        if (kb + 1 < NKB) { TF32_STORE(cur ^ 1, pa0, pa1, pb0) }
        __syncthreads();
    }

#pragma unroll
    for (int mt = 0; mt < 2; mt++) {
        const int r0 = m0 + wm*32 + mt*16 + fg;
        const int r1 = r0 + 8;
#pragma unroll
        for (int nt = 0; nt < 4; nt++) {
            const int col = n0 + wn*32 + nt*8 + fc*2;
            const int nh = col >> 7, d = col & 127;
            float *o0, *o1;
            if (WHICH == 0) {
                int b = r0 >> 10, mm = r0 & 1023;
                o0 = g_q + (((size_t)(b*NHEAD + nh) * SEQ_M + mm) * DHEAD + d);
                b = r1 >> 10; mm = r1 & 1023;
                o1 = g_q + (((size_t)(b*NHEAD + nh) * SEQ_M + mm) * DHEAD + d);
            } else {
                float* base = (WHICH == 1) ? g_k : g_v;
                int b = r0 >> 11, t = r0 & 2047;
                o0 = base + (((size_t)(b*NHEAD + nh) * LT + t) * DHEAD + d);
                b = r1 >> 11; t = r1 & 2047;
                o1 = base + (((size_t)(b*NHEAD + nh) * LT + t) * DHEAD + d);
            }
            *(float2*)o0 = make_float2(acc[mt][nt][0], acc[mt][nt][1]);
            *(float2*)o1 = make_float2(acc[mt][nt][2], acc[mt][nt][3]);
        }
    }
}

// ---------------- banded scores (fp32) --------------------------------------------
__global__ void __launch_bounds__(256) k_scores(const float* __restrict__ pos)
{
    __shared__ float Qs[16][64];
    __shared__ float Ks[16][128];
    __shared__ float Ps[16][64];
    const int bh = blockIdx.z;
    const int i0 = blockIdx.y * 64, j0 = blockIdx.x * 64;
    const int tid = threadIdx.x, ty = tid >> 4, tx = tid & 15;

    const float* qbase = g_q + (size_t)bh * SEQ_M * DHEAD;
    const float* kbase = g_k + (size_t)bh * LT * DHEAD;

    const int qi = tid >> 2, qk = (tid & 3) * 4;
    const int kr = tid >> 1, kk8 = (tid & 1) * 8;
    const int pk = tid >> 4, pj = (tid & 15) * 4;

    float acc[4][4] = {};
    for (int dc = 0; dc < DHEAD; dc += 16) {
        float4 qv = *(const float4*)(qbase + (size_t)(i0 + qi) * DHEAD + dc + qk);
        Qs[qk+0][qi] = qv.x; Qs[qk+1][qi] = qv.y;
        Qs[qk+2][qi] = qv.z; Qs[qk+3][qi] = qv.w;
        float4 k0 = *(const float4*)(kbase + (size_t)(i0 + j0 + kr) * DHEAD + dc + kk8);
        float4 k1 = *(const float4*)(kbase + (size_t)(i0 + j0 + kr) * DHEAD + dc + kk8 + 4);
        Ks[kk8+0][kr] = k0.x; Ks[kk8+1][kr] = k0.y; Ks[kk8+2][kr] = k0.z; Ks[kk8+3][kr] = k0.w;
        Ks[kk8+4][kr] = k1.x; Ks[kk8+5][kr] = k1.y; Ks[kk8+6][kr] = k1.z; Ks[kk8+7][kr] = k1.w;
        *(float4*)&Ps[pk][pj] = *(const float4*)(pos + (size_t)(dc + pk) * SEQ_L + j0 + pj);
        __syncthreads();
#pragma unroll
        for (int kk = 0; kk < 16; kk++) {
            float4 q4 = *(const float4*)&Qs[kk][ty*4];
            float4 p4 = *(const float4*)&Ps[kk][tx*4];
            const int base = (ty + tx) * 4;
            float4 ka = *(const float4*)&Ks[kk][base];
            float4 kb2 = *(const float4*)&Ks[kk][base + 4];
            float qr[4] = {q4.x,q4.y,q4.z,q4.w};
            float pr[4] = {p4.x,p4.y,p4.z,p4.w};
            float kv[8] = {ka.x,ka.y,ka.z,ka.w,kb2.x,kb2.y,kb2.z,kb2.w};
#pragma unroll
            for (int i = 0; i < 4; i++)
#pragma unroll
                for (int j = 0; j < 4; j++)
                    acc[i][j] = fmaf(qr[i], kv[i+j] + pr[j], acc[i][j]);
        }
        __syncthreads();
    }
    const float scale = 1.0f / 32.0f;
#pragma unroll
    for (int i = 0; i < 4; i++) {
        const int row = i0 + ty*4 + i;
        *(float4*)(g_s + ((size_t)bh * SEQ_M + row) * SEQ_L + j0 + tx*4) =
            make_float4(acc[i][0]*scale, acc[i][1]*scale, acc[i][2]*scale, acc[i][3]*scale);
    }
}

// ---------------- softmax ----------------------------------------------------------
__global__ void __launch_bounds__(256) k_softmax()
{
    __shared__ float sbuf[8];
    const size_t row = blockIdx.x;
    float* p = g_s + row * SEQ_L;
    const int c0 = threadIdx.x * 4;
    float4 v = *(const float4*)(p + c0);
    float mx = fmaxf(fmaxf(v.x, v.y), fmaxf(v.z, v.w));
    mx = blk_max8(mx, sbuf);
    float e0 = __expf(v.x - mx), e1 = __expf(v.y - mx);
    float e2 = __expf(v.z - mx), e3 = __expf(v.w - mx);
    float s = blk_sum8(e0 + e1 + e2 + e3, sbuf);
    const float inv = 1.0f / s;
    *(float4*)(p + c0) = make_float4(e0*inv, e1*inv, e2*inv, e3*inv);
}

// ---------------- banded AV (fp32) ----------------------------------------------------
__global__ void __launch_bounds__(256) k_av()
{
    __shared__ float As[16][64];
    __shared__ float Vs[16][64];
    const int bh = blockIdx.z;
    const int i0 = blockIdx.y * 64;
    const int d0 = blockIdx.x * 64;
    const int tid = threadIdx.x, ty = tid >> 4, tx = tid & 15;

    const float* abase = g_s + (size_t)bh * SEQ_M * SEQ_L;
    const float* vbase = g_v + (size_t)bh * LT * DHEAD;

    const int ail = tid >> 2;
    const int ar4 = (tid & 3) * 4;
    const float* arow_ptr = abase + (size_t)(i0 + ail) * SEQ_L;
    const int vr = tid >> 4, vd4 = (tid & 15) * 4;

    float acc[4][4] = {};
    for (int ch = 0; ch < (64 + SEQ_L) / 16; ch++) {
        const int ch16 = ch * 16;
        const int r0c = i0 + ch16;
#pragma unroll
        for (int u = 0; u < 4; u++) {
            const int rr = ar4 + u;
            const int j = ch16 + rr - ail;
            As[rr][ail] = (j >= 0 && j < SEQ_L) ? arow_ptr[j] : 0.0f;
        }
        *(float4*)&Vs[vr][vd4] =
            *(const float4*)(vbase + (size_t)(r0c + vr) * DHEAD + d0 + vd4);
        __syncthreads();
#pragma unroll
        for (int rr = 0; rr < 16; rr++) {
            float4 a4 = *(const float4*)&As[rr][ty*4];
            float4 v4 = *(const float4*)&Vs[rr][tx*4];
            float ar[4] = {a4.x,a4.y,a4.z,a4.w};
            float vv[4] = {v4.x,v4.y,v4.z,v4.w};
#pragma unroll
            for (int i = 0; i < 4; i++)
#pragma unroll
                for (int j = 0; j < 4; j++)
                    acc[i][j] = fmaf(ar[i], vv[j], acc[i][j]);
        }
        __syncthreads();
    }
    const int b = bh >> 3, nh = bh & 7;
#pragma unroll
    for (int i = 0; i < 4; i++) {
        const int row = i0 + ty*4 + i;
        *(float4*)(g_ao + ((size_t)(b * SEQ_M + row)) * HDIM + nh * DHEAD + d0 + tx*4) =
            make_float4(acc[i][0], acc[i][1], acc[i][2], acc[i][3]);
    }
}

// ---------------- Wo projection + residual (tf32 tensor) ------------------------------
__global__ void __launch_bounds__(256, 3) k_wo(const float* __restrict__ Wo,
                                               const float* __restrict__ h)
{
    __shared__ float As[2][16][136];
    __shared__ float Bs[2][16][72];
    TF32_DECLS
    const int m0 = blockIdx.y * 128, n0 = blockIdx.x * 64;

    const float* aptr = g_ao + (size_t)(m0 + alm) * HDIM;
    const float* bptr = Wo + (size_t)blkr * HDIM + n0 + bln;

    float4 pa0 = *(const float4*)(aptr + alk);
    float4 pa1 = *(const float4*)(aptr + alk + 4);
    float4 pb0 = *(const float4*)(bptr);
    TF32_STORE(0, pa0, pa1, pb0)
    __syncthreads();

    float acc[2][4][4] = {};
    const int NKB = HDIM / 16;
    for (int kb = 0; kb < NKB; kb++) {
        const int cur = kb & 1;
        if (kb + 1 < NKB) {
            pa0 = *(const float4*)(aptr + (kb+1)*16 + alk);
            pa1 = *(const float4*)(aptr + (kb+1)*16 + alk + 4);
            pb0 = *(const float4*)(bptr + (size_t)(kb+1)*16 * HDIM);
        }
        TF32_COMPUTE(cur)
        if (kb + 1 < NKB) { TF32_STORE(cur ^ 1, pa0, pa1, pb0) }
        __syncthreads();
    }

#pragma unroll
    for (int mt = 0; mt < 2; mt++) {
        const int r0 = m0 + wm*32 + mt*16 + fg;
        const int r1 = r0 + 8;
#pragma unroll
        for (int nt = 0; nt < 4; nt++) {
            const int col = n0 + wn*32 + nt*8 + fc*2;
            float2 h0 = *(const float2*)(h + (size_t)r0 * HDIM + col);
            float2 h1 = *(const float2*)(h + (size_t)r1 * HDIM + col);
            *(float2*)(g_t1 + (size_t)r0 * HDIM + col) =
                make_float2(acc[mt][nt][0] + h0.x, acc[mt][nt][1] + h0.y);
            *(float2*)(g_t1 + (size_t)r1 * HDIM + col) =
                make_float2(acc[mt][nt][2] + h1.x, acc[mt][nt][3] + h1.y);
        }
    }
}

// ---------------- LN1 ---------------------------------------------------------------
__global__ void __launch_bounds__(256) k_ln1(const float* __restrict__ g,
                                             const float* __restrict__ b)
{
    __shared__ float sbuf[8];
    const int row = blockIdx.x;
    const int c0 = threadIdx.x * 4;
    float4 xv = *(const float4*)(g_t1 + (size_t)row * HDIM + c0);
    float s  = xv.x + xv.y + xv.z + xv.w;
    float s2 = xv.x*xv.x + xv.y*xv.y + xv.z*xv.z + xv.w*xv.w;
    s  = blk_sum8(s,  sbuf);
    s2 = blk_sum8(s2, sbuf);
    const float mu = s * (1.0f / HDIM);
    const float var = s2 * (1.0f / HDIM) - mu * mu;
    const float inv = rsqrtf(var + 1e-5f);
    float4 gv = *(const float4*)(g + c0);
    float4 bv = *(const float4*)(b + c0);
    *(float4*)(g_h1 + (size_t)row * HDIM + c0) = make_float4(
        (xv.x - mu) * inv * gv.x + bv.x,
        (xv.y - mu) * inv * gv.y + bv.y,
        (xv.z - mu) * inv * gv.z + bv.z,
        (xv.w - mu) * inv * gv.w + bv.w);
}

// ---------------- gating --------------------------------------------------------------
__global__ void __launch_bounds__(256) k_gate(const float* __restrict__ gw,
                                              const float* __restrict__ gb)
{
    __shared__ float lg[NEXP];
    const int t = blockIdx.x;
    const float* x = g_h1 + (size_t)t * HDIM;
    const int tid = threadIdx.x, w = tid >> 5, lane = tid & 31;
    float s = 0.0f;
    for (int hh = lane; hh < HDIM; hh += 32)
        s = fmaf(x[hh], gw[hh * NEXP + w], s);
#pragma unroll
    for (int o = 16; o; o >>= 1) s += __shfl_xor_sync(0xffffffffu, s, o);
    if (lane == 0) lg[w] = s + gb[w];
    __syncthreads();
    if (tid == 0) {
        int i0 = 0;
        for (int e = 1; e < NEXP; e++) if (lg[e] > lg[i0]) i0 = e;
        int i1 = -1;
        for (int e = 0; e < NEXP; e++) {
            if (e == i0) continue;
            if (i1 < 0 || lg[e] > lg[i1]) i1 = e;
        }
        const float e1 = __expf(lg[i1] - lg[i0]);
        const float den = 1.0f / (1.0f + e1);
        g_top_e[2*t]   = i0; g_top_e[2*t+1] = i1;
        g_top_w[2*t]   = den;
        g_top_w[2*t+1] = e1 * den;
        atomicAdd(&g_cnt[i0], 1);
        atomicAdd(&g_cnt[i1], 1);
    }
}

__global__ void k_scan()
{
    int s = 0;
    for (int e = 0; e < NEXP; e++) { g_off[e] = s; s += g_cnt[e]; }
}

__global__ void __launch_bounds__(256) k_scatter()
{
    const int t = blockIdx.x * 256 + threadIdx.x;
    if (t >= NTOK) return;
#pragma unroll
    for (int k = 0; k < 2; k++) {
        const int e = g_top_e[2*t + k];
        const int p = atomicAdd(&g_cur[e], 1);
        const int pos = g_off[e] + p;
        g_slot_token[pos] = t;
        g_slot_w[pos] = g_top_w[2*t + k];
        g_token_slot[2*t + k] = pos;
    }
}

// ---------------- MoE GEMM1 (tf32 tensor) ----------------------------------------------
__global__ void __launch_bounds__(256, 3) k_moe1(const float* __restrict__ w1,
                                                 const float* __restrict__ b1)
{
    const int e = blockIdx.z;
    const int cnt = g_cnt[e];
    const int r0b = blockIdx.y * 128;
    if (r0b >= cnt) return;
    const int off = g_off[e];

    __shared__ float As[2][16][136];
    __shared__ float Bs[2][16][72];
    __shared__ int toks[128];
    TF32_DECLS
    const int n0 = blockIdx.x * 64;
    const float4 z4 = make_float4(0.f, 0.f, 0.f, 0.f);

    if (tid < 128) {
        const int r = r0b + tid;
        toks[tid] = (r < cnt) ? g_slot_token[off + r] : -1;
    }
    __syncthreads();
    const int tok = toks[alm];
    const bool aval = (tok >= 0);
    const float* aptr = g_h1 + (size_t)(aval ? tok : 0) * HDIM;
    const float* bptr = w1 + (size_t)e * HDIM * FDIM + (size_t)blkr * FDIM + n0 + bln;

    float4 pa0 = aval ? *(const float4*)(aptr + alk) : z4;
    float4 pa1 = aval ? *(const float4*)(aptr + alk + 4) : z4;
    float4 pb0 = *(const float4*)(bptr);
    TF32_STORE(0, pa0, pa1, pb0)
    __syncthreads();

    float acc[2][4][4] = {};
    const int NKB = HDIM / 16;
    for (int kb = 0; kb < NKB; kb++) {
        const int cur = kb & 1;
        if (kb + 1 < NKB) {
            pa0 = aval ? *(const float4*)(aptr + (kb+1)*16 + alk) : z4;
            pa1 = aval ? *(const float4*)(aptr + (kb+1)*16 + alk + 4) : z4;
            pb0 = *(const float4*)(bptr + (size_t)(kb+1)*16 * FDIM);
        }
        TF32_COMPUTE(cur)
        if (kb + 1 < NKB) { TF32_STORE(cur ^ 1, pa0, pa1, pb0) }
        __syncthreads();
    }

#pragma unroll
    for (int mt = 0; mt < 2; mt++) {
        const int r0 = r0b + wm*32 + mt*16 + fg;
        const int r1 = r0 + 8;
#pragma unroll
        for (int nt = 0; nt < 4; nt++) {
            const int col = n0 + wn*32 + nt*8 + fc*2;
            float2 bb = *(const float2*)(b1 + (size_t)e * FDIM + col);
            if (r0 < cnt)
                *(float2*)(g_hidden + (size_t)(off + r0) * FDIM + col) =
                    make_float2(fmaxf(acc[mt][nt][0] + bb.x, 0.f),
                                fmaxf(acc[mt][nt][1] + bb.y, 0.f));
            if (r1 < cnt)
                *(float2*)(g_hidden + (size_t)(off + r1) * FDIM + col) =
                    make_float2(fmaxf(acc[mt][nt][2] + bb.x, 0.f),
                                fmaxf(acc[mt][nt][3] + bb.y, 0.f));
        }
    }
}

// ---------------- MoE GEMM2 (tf32 tensor) ------------------------------------------------
__global__ void __launch_bounds__(256, 3) k_moe2(const float* __restrict__ w2,
                                                 const float* __restrict__ b2)
{
    const int e = blockIdx.z;
    const int cnt = g_cnt[e];
    const int r0b = blockIdx.y * 128;
    if (r0b >= cnt) return;
    const int off = g_off[e];

    __shared__ float As[2][16][136];
    __shared__ float Bs[2][16][72];
    TF32_DECLS
    const int n0 = blockIdx.x * 64;
    const float4 z4 = make_float4(0.f, 0.f, 0.f, 0.f);

    const int r = r0b + alm;
    const bool aval = (r < cnt);
    const float* aptr = g_hidden + (size_t)(off + (aval ? r : 0)) * FDIM;
    const float* bptr = w2 + (size_t)e * FDIM * HDIM + (size_t)blkr * HDIM + n0 + bln;

    float4 pa0 = aval ? *(const float4*)(aptr + alk) : z4;
    float4 pa1 = aval ? *(const float4*)(aptr + alk + 4) : z4;
    float4 pb0 = *(const float4*)(bptr);
    TF32_STORE(0, pa0, pa1, pb0)
    __syncthreads();

    float acc[2][4][4] = {};
    const int NKB = FDIM / 16;
    for (int kb = 0; kb < NKB; kb++) {
        const int cur = kb & 1;
        if (kb + 1 < NKB) {
            pa0 = aval ? *(const float4*)(aptr + (kb+1)*16 + alk) : z4;
            pa1 = aval ? *(const float4*)(aptr + (kb+1)*16 + alk + 4) : z4;
            pb0 = *(const float4*)(bptr + (size_t)(kb+1)*16 * HDIM);
        }
        TF32_COMPUTE(cur)
        if (kb + 1 < NKB) { TF32_STORE(cur ^ 1, pa0, pa1, pb0) }
        __syncthreads();
    }

#pragma unroll
    for (int mt = 0; mt < 2; mt++) {
        const int r0 = r0b + wm*32 + mt*16 + fg;
        const int r1 = r0 + 8;
#pragma unroll
        for (int nt = 0; nt < 4; nt++) {
            const int col = n0 + wn*32 + nt*8 + fc*2;
            float2 bb = *(const float2*)(b2 + (size_t)e * HDIM + col);
            if (r0 < cnt)
                *(float2*)(g_y + (size_t)(off + r0) * HDIM + col) =
                    make_float2(acc[mt][nt][0] + bb.x, acc[mt][nt][1] + bb.y);
            if (r1 < cnt)
                *(float2*)(g_y + (size_t)(off + r1) * HDIM + col) =
                    make_float2(acc[mt][nt][2] + bb.x, acc[mt][nt][3] + bb.y);
        }
    }
}

// ---------------- combine + LN2 -----------------------------------------------------------
__global__ void __launch_bounds__(256) k_combine(const float* __restrict__ mom_in,
                                                 const float* __restrict__ g,
                                                 const float* __restrict__ b,
                                                 float* __restrict__ out)
{
    __shared__ float sbuf[8];
    const int t = blockIdx.x;
    const int s0 = g_token_slot[2*t], s1 = g_token_slot[2*t + 1];
    const float w0 = g_slot_w[s0], w1 = g_slot_w[s1];
    const int c0 = threadIdx.x * 4;

    float4 h1v = *(const float4*)(g_h1 + (size_t)t * HDIM + c0);
    float4 mv  = *(const float4*)(mom_in + (size_t)t * HDIM + c0);
    float4 y0  = *(const float4*)(g_y + (size_t)s0 * HDIM + c0);
    float4 y1  = *(const float4*)(g_y + (size_t)s1 * HDIM + c0);

    float momn[4], x[4];
    momn[0] = 0.7f*mv.x + w0*y0.x + w1*y1.x;
    momn[1] = 0.7f*mv.y + w0*y0.y + w1*y1.y;
    momn[2] = 0.7f*mv.z + w0*y0.z + w1*y1.z;
    momn[3] = 0.7f*mv.w + w0*y0.w + w1*y1.w;
    x[0] = h1v.x - momn[0]; x[1] = h1v.y - momn[1];
    x[2] = h1v.z - momn[2]; x[3] = h1v.w - momn[3];

    float s  = x[0] + x[1] + x[2] + x[3];
    float s2 = x[0]*x[0] + x[1]*x[1] + x[2]*x[2] + x[3]*x[3];
    s  = blk_sum8(s,  sbuf);
    s2 = blk_sum8(s2, sbuf);
    const float mu = s * (1.0f / HDIM);
    const float var = s2 * (1.0f / HDIM) - mu * mu;
    const float inv = rsqrtf(var + 1e-5f);
    float4 gv = *(const float4*)(g + c0);
    float4 bv = *(const float4*)(b + c0);

    *(float4*)(out + (size_t)t * HDIM + c0) = make_float4(
        (x[0] - mu) * inv * gv.x + bv.x,
        (x[1] - mu) * inv * gv.y + bv.y,
        (x[2] - mu) * inv * gv.z + bv.z,
        (x[3] - mu) * inv * gv.w + bv.w);
    *(float4*)(out + (size_t)NTOK * HDIM + (size_t)t * HDIM + c0) =
        make_float4(momn[0], momn[1], momn[2], momn[3]);
}

// ---------------- launch ---------------------------------------------------------------------
extern "C" void kernel_launch(void* const* d_in, const int* in_sizes, int n_in,
                              void* d_out, int out_size)
{
    const float* h       = (const float*)d_in[0];
    const float* h_cache = (const float*)d_in[1];
    const float* pos     = (const float*)d_in[2];
    const float* mom     = (const float*)d_in[3];
    const float* Wq      = (const float*)d_in[4];
    const float* Wk      = (const float*)d_in[5];
    const float* Wv      = (const float*)d_in[6];
    const float* Wo      = (const float*)d_in[7];
    const float* gate_w  = (const float*)d_in[8];
    const float* gate_b  = (const float*)d_in[9];
    const float* w1      = (const float*)d_in[10];
    const float* b1      = (const float*)d_in[11];
    const float* w2      = (const float*)d_in[12];
    const float* b2      = (const float*)d_in[13];
    const float* ln1g    = (const float*)d_in[14];
    const float* ln1b    = (const float*)d_in[15];
    const float* ln2g    = (const float*)d_in[16];
    const float* ln2b    = (const float*)d_in[17];
    float* out = (float*)d_out;

    k_init<<<1, 32>>>();
    k_proj<0><<<dim3(HDIM/64, NTOK/128), 256>>>(h, h_cache, Wq);
    k_proj<1><<<dim3(HDIM/64, (BATCH*LT)/128), 256>>>(h, h_cache, Wk);
    k_proj<2><<<dim3(HDIM/64, (BATCH*LT)/128), 256>>>(h, h_cache, Wv);
    k_scores<<<dim3(SEQ_L/64, SEQ_M/64, NBH), 256>>>(pos);
    k_softmax<<<NBH*SEQ_M, 256>>>();
    k_av<<<dim3(DHEAD/64, SEQ_M/64, NBH), 256>>>();
    k_wo<<<dim3(HDIM/64, NTOK/128), 256>>>(Wo, h);
    k_ln1<<<NTOK, 256>>>(ln1g, ln1b);
    k_gate<<<NTOK, 256>>>(gate_w, gate_b);
    k_scan<<<1, 1>>>();
    k_scatter<<<NTOK/256, 256>>>();
    k_moe1<<<dim3(FDIM/64, NSLOT/128, NEXP), 256>>>(w1, b1);
    k_moe2<<<dim3(HDIM/64, NSLOT/128, NEXP), 256>>>(w2, b2);
    k_combine<<<NTOK, 256>>>(mom, ln2g, ln2b, out);
}

// round 11
// speedup vs baseline: 1.5227x; 1.2824x over previous
#include <cuda_runtime.h>
#include <math.h>

#define BATCH 4
#define SEQ_M 1024
#define HDIM  1024
#define NHEAD 8
#define DHEAD 128
#define SEQ_L 1024
#define NEXP  8
#define FDIM  4096
#define NTOK  (BATCH*SEQ_M)
#define NBH   (BATCH*NHEAD)
#define LT    (SEQ_L+SEQ_M)
#define NSLOT (NTOK*2)

// ---------------- scratch (device globals) -------------------------------------
__device__ float g_q[(size_t)NBH*SEQ_M*DHEAD];
__device__ float g_k[(size_t)NBH*LT*DHEAD];
__device__ float g_v[(size_t)NBH*LT*DHEAD];
__device__ float g_s[(size_t)NBH*SEQ_M*SEQ_L];
__device__ float g_ao[(size_t)NTOK*HDIM];
__device__ float g_t1[(size_t)NTOK*HDIM];
__device__ float g_h1[(size_t)NTOK*HDIM];
__device__ float g_hidden[(size_t)NSLOT*FDIM];
__device__ float g_y[(size_t)NSLOT*HDIM];
__device__ int   g_cnt[NEXP];
__device__ int   g_cur[NEXP];
__device__ int   g_off[NEXP];
__device__ int   g_slot_token[NSLOT];
__device__ float g_slot_w[NSLOT];
__device__ int   g_token_slot[NTOK*2];
__device__ int   g_top_e[NTOK*2];
__device__ float g_top_w[NTOK*2];

// ---------------- tf32 helpers -----------------------------------------------
__device__ __forceinline__ unsigned f2tf(float x)
{
    unsigned y;
    asm("cvt.rna.tf32.f32 %0, %1;" : "=r"(y) : "f"(x));
    return y;
}
__device__ __forceinline__ float4 tf4(float4 v)
{
    return make_float4(__uint_as_float(f2tf(v.x)), __uint_as_float(f2tf(v.y)),
                       __uint_as_float(f2tf(v.z)), __uint_as_float(f2tf(v.w)));
}

#define MMA_TF32(d0,d1,d2,d3,a0,a1,a2,a3,b0,b1)                             \
    asm volatile("mma.sync.aligned.m16n8k8.row.col.f32.tf32.tf32.f32 "      \
        "{%0,%1,%2,%3}, {%4,%5,%6,%7}, {%8,%9}, {%0,%1,%2,%3};"             \
        : "+f"(d0),"+f"(d1),"+f"(d2),"+f"(d3)                               \
        : "r"(a0),"r"(a1),"r"(a2),"r"(a3),"r"(b0),"r"(b1));

// ---------------- tf32 128x128x16 GEMM building blocks (proven R4) -------------
#define TF32_DECLS                                                           \
    const int tid = threadIdx.x, lane = tid & 31, warp = tid >> 5;           \
    const int wm = warp >> 1, wn = warp & 1;                                 \
    const int fg = lane >> 2, fc = lane & 3;                                 \
    const int alm = tid & 127, alk = (tid >> 7) * 8;                         \
    const int blkr = tid >> 5, bln = lane * 4;

#define TF32_STORE(buf, PA0, PA1, PB0, PB1)                                  \
    { const float* _p0 = (const float*)&(PA0);                              \
      const float* _p1 = (const float*)&(PA1);                              \
      _Pragma("unroll")                                                      \
      for (int i = 0; i < 4; i++) {                                          \
          As[buf][alk+i][alm]   = __uint_as_float(f2tf(_p0[i]));             \
          As[buf][alk+4+i][alm] = __uint_as_float(f2tf(_p1[i]));             \
      }                                                                      \
      *(float4*)&Bs[buf][blkr][bln]   = tf4(PB0);                            \
      *(float4*)&Bs[buf][blkr+8][bln] = tf4(PB1); }

#define TF32_COMPUTE(cur)                                                    \
    _Pragma("unroll")                                                        \
    for (int k8 = 0; k8 < 16; k8 += 8) {                                     \
        unsigned afr[2][4], bfr[8][2];                                       \
        _Pragma("unroll")                                                    \
        for (int mt = 0; mt < 2; mt++) {                                     \
            const int mr = wm*32 + mt*16 + fg;                               \
            afr[mt][0] = __float_as_uint(As[cur][k8+fc  ][mr]);              \
            afr[mt][1] = __float_as_uint(As[cur][k8+fc  ][mr+8]);            \
            afr[mt][2] = __float_as_uint(As[cur][k8+fc+4][mr]);              \
            afr[mt][3] = __float_as_uint(As[cur][k8+fc+4][mr+8]);            \
        }                                                                    \
        _Pragma("unroll")                                                    \
        for (int nt = 0; nt < 8; nt++) {                                     \
            const int nc = wn*64 + nt*8 + fg;                                \
            bfr[nt][0] = __float_as_uint(Bs[cur][k8+fc  ][nc]);              \
            bfr[nt][1] = __float_as_uint(Bs[cur][k8+fc+4][nc]);              \
        }                                                                    \
        _Pragma("unroll")                                                    \
        for (int mt = 0; mt < 2; mt++)                                       \
        _Pragma("unroll")                                                    \
        for (int nt = 0; nt < 8; nt++)                                       \
            MMA_TF32(acc[mt][nt][0],acc[mt][nt][1],acc[mt][nt][2],           \
                     acc[mt][nt][3],                                         \
                     afr[mt][0],afr[mt][1],afr[mt][2],afr[mt][3],            \
                     bfr[nt][0],bfr[nt][1]);                                 \
    }

// ---------------- block reductions (256 threads / 8 warps) --------------------
__device__ __forceinline__ float blk_sum8(float v, float* sbuf)
{
    const int lane = threadIdx.x & 31, w = threadIdx.x >> 5;
#pragma unroll
    for (int o = 16; o; o >>= 1) v += __shfl_xor_sync(0xffffffffu, v, o);
    __syncthreads();
    if (lane == 0) sbuf[w] = v;
    __syncthreads();
    return sbuf[0]+sbuf[1]+sbuf[2]+sbuf[3]+sbuf[4]+sbuf[5]+sbuf[6]+sbuf[7];
}

__device__ __forceinline__ float blk_max8(float v, float* sbuf)
{
    const int lane = threadIdx.x & 31, w = threadIdx.x >> 5;
#pragma unroll
    for (int o = 16; o; o >>= 1) v = fmaxf(v, __shfl_xor_sync(0xffffffffu, v, o));
    __syncthreads();
    if (lane == 0) sbuf[w] = v;
    __syncthreads();
    return fmaxf(fmaxf(fmaxf(sbuf[0],sbuf[1]),fmaxf(sbuf[2],sbuf[3])),
                 fmaxf(fmaxf(sbuf[4],sbuf[5]),fmaxf(sbuf[6],sbuf[7])));
}

// ---------------- init ----------------------------------------------------------
__global__ void k_init()
{
    int t = threadIdx.x;
    if (t < NEXP) { g_cnt[t] = 0; g_cur[t] = 0; }
}

// ---------------- QKV projections (tf32 tensor, proven) --------------------------
template<int WHICH>
__global__ void __launch_bounds__(256) k_proj(
    const float* __restrict__ h, const float* __restrict__ h_cache,
    const float* __restrict__ W)
{
    __shared__ float As[2][16][136];
    __shared__ float Bs[2][16][136];
    TF32_DECLS
    const int m0 = blockIdx.y * 128, n0 = blockIdx.x * 128;

    const int arow = m0 + alm;
    const float* aptr;
    if (WHICH == 0) {
        aptr = h + (size_t)arow * HDIM;
    } else {
        const int b = arow >> 11, t = arow & 2047;
        aptr = (t < SEQ_L) ? (h_cache + ((size_t)b * SEQ_L + t) * HDIM)
                           : (h + ((size_t)b * SEQ_M + (t - SEQ_L)) * HDIM);
    }
    const float* bptr = W + (size_t)blkr * HDIM + n0 + bln;

    float4 pa0 = *(const float4*)(aptr + alk);
    float4 pa1 = *(const float4*)(aptr + alk + 4);
    float4 pb0 = *(const float4*)(bptr);
    float4 pb1 = *(const float4*)(bptr + (size_t)8 * HDIM);
    TF32_STORE(0, pa0, pa1, pb0, pb1)
    __syncthreads();

    float acc[2][8][4] = {};
    const int NKB = HDIM / 16;
    for (int kb = 0; kb < NKB; kb++) {
        const int cur = kb & 1;
        if (kb + 1 < NKB) {
            pa0 = *(const float4*)(aptr + (kb+1)*16 + alk);
            pa1 = *(const float4*)(aptr + (kb+1)*16 + alk + 4);
            pb0 = *(const float4*)(bptr + (size_t)(kb+1)*16 * HDIM);
            pb1 = *(const float4*)(bptr + (size_t)((kb+1)*16 + 8) * HDIM);
        }
        TF32_COMPUTE(cur)
        if (kb + 1 < NKB) { TF32_STORE(cur ^ 1, pa0, pa1, pb0, pb1) }
        __syncthreads();
    }

#pragma unroll
    for (int mt = 0; mt < 2; mt++) {
        const int r0 = m0 + wm*32 + mt*16 + fg;
        const int r1 = r0 + 8;
#pragma unroll
        for (int nt = 0; nt < 8; nt++) {
            const int col = n0 + wn*64 + nt*8 + fc*2;
            const int nh = col >> 7, d = col & 127;
            float *o0, *o1;
            if (WHICH == 0) {
                int b = r0 >> 10, mm = r0 & 1023;
                o0 = g_q + (((size_t)(b*NHEAD + nh) * SEQ_M + mm) * DHEAD + d);
                b = r1 >> 10; mm = r1 & 1023;
                o1 = g_q + (((size_t)(b*NHEAD + nh) * SEQ_M + mm) * DHEAD + d);
            } else {
                float* base = (WHICH == 1) ? g_k : g_v;
                int b = r0 >> 11, t = r0 & 2047;
                o0 = base + (((size_t)(b*NHEAD + nh) * LT + t) * DHEAD + d);
                b = r1 >> 11; t = r1 & 2047;
                o1 = base + (((size_t)(b*NHEAD + nh) * LT + t) * DHEAD + d);
            }
            *(float2*)o0 = make_float2(acc[mt][nt][0], acc[mt][nt][1]);
            *(float2*)o1 = make_float2(acc[mt][nt][2], acc[mt][nt][3]);
        }
    }
}

// ---------------- banded scores v2: 128(i) x 64(j) tile, 8x4 microtile ------------
__global__ void __launch_bounds__(256) k_scores(const float* __restrict__ pos)
{
    __shared__ float Qs[16][128];
    __shared__ float Ks[16][192];
    __shared__ float Ps[16][64];
    const int bh = blockIdx.z;
    const int i0 = blockIdx.y * 128, j0 = blockIdx.x * 64;
    const int tid = threadIdx.x, ty = tid >> 4, tx = tid & 15;

    const float* qbase = g_q + (size_t)bh * SEQ_M * DHEAD;
    const float* kbase = g_k + (size_t)bh * LT * DHEAD;

    const int qi = tid >> 1, qk = (tid & 1) * 8;   // Q: 128 rows x 16d
    const int pk = tid >> 4, pj = (tid & 15) * 4;  // P: 16d x 64j
    const int kr = tid >> 1, kk8 = (tid & 1) * 8;  // K pass1: 128 keys

    float acc[8][4] = {};
    for (int dc = 0; dc < DHEAD; dc += 16) {
        float4 q0 = *(const float4*)(qbase + (size_t)(i0+qi)*DHEAD + dc + qk);
        float4 q1 = *(const float4*)(qbase + (size_t)(i0+qi)*DHEAD + dc + qk + 4);
        Qs[qk+0][qi]=q0.x; Qs[qk+1][qi]=q0.y; Qs[qk+2][qi]=q0.z; Qs[qk+3][qi]=q0.w;
        Qs[qk+4][qi]=q1.x; Qs[qk+5][qi]=q1.y; Qs[qk+6][qi]=q1.z; Qs[qk+7][qi]=q1.w;

        float4 k0 = *(const float4*)(kbase + (size_t)(i0+j0+kr)*DHEAD + dc + kk8);
        float4 k1 = *(const float4*)(kbase + (size_t)(i0+j0+kr)*DHEAD + dc + kk8 + 4);
        Ks[kk8+0][kr]=k0.x; Ks[kk8+1][kr]=k0.y; Ks[kk8+2][kr]=k0.z; Ks[kk8+3][kr]=k0.w;
        Ks[kk8+4][kr]=k1.x; Ks[kk8+5][kr]=k1.y; Ks[kk8+6][kr]=k1.z; Ks[kk8+7][kr]=k1.w;
        if (tid < 128) {
            const int kr2 = 128 + (tid >> 1);
            const int kb2 = (tid & 1) * 8;
            float4 m0v = *(const float4*)(kbase + (size_t)(i0+j0+kr2)*DHEAD + dc + kb2);
            float4 m1v = *(const float4*)(kbase + (size_t)(i0+j0+kr2)*DHEAD + dc + kb2 + 4);
            Ks[kb2+0][kr2]=m0v.x; Ks[kb2+1][kr2]=m0v.y; Ks[kb2+2][kr2]=m0v.z; Ks[kb2+3][kr2]=m0v.w;
            Ks[kb2+4][kr2]=m1v.x; Ks[kb2+5][kr2]=m1v.y; Ks[kb2+6][kr2]=m1v.z; Ks[kb2+7][kr2]=m1v.w;
        }
        *(float4*)&Ps[pk][pj] = *(const float4*)(pos + (size_t)(dc + pk) * SEQ_L + j0 + pj);
        __syncthreads();

        const int base = ty*8 + tx*4;
#pragma unroll
        for (int kk = 0; kk < 16; kk++) {
            float4 a0 = *(const float4*)&Qs[kk][ty*8];
            float4 a1 = *(const float4*)&Qs[kk][ty*8+4];
            float4 p4 = *(const float4*)&Ps[kk][tx*4];
            float4 kA = *(const float4*)&Ks[kk][base];
            float4 kB = *(const float4*)&Ks[kk][base+4];
            float4 kC = *(const float4*)&Ks[kk][base+8];
            float q8[8] = {a0.x,a0.y,a0.z,a0.w,a1.x,a1.y,a1.z,a1.w};
            float pr[4] = {p4.x,p4.y,p4.z,p4.w};
            float kv[12] = {kA.x,kA.y,kA.z,kA.w,kB.x,kB.y,kB.z,kB.w,
                            kC.x,kC.y,kC.z,kC.w};
#pragma unroll
            for (int i = 0; i < 8; i++)
#pragma unroll
                for (int j = 0; j < 4; j++)
                    acc[i][j] = fmaf(q8[i], kv[i+j] + pr[j], acc[i][j]);
        }
        __syncthreads();
    }
    const float scale = 1.0f / 32.0f;
#pragma unroll
    for (int i = 0; i < 8; i++) {
        const int row = i0 + ty*8 + i;
        *(float4*)(g_s + ((size_t)bh * SEQ_M + row) * SEQ_L + j0 + tx*4) =
            make_float4(acc[i][0]*scale, acc[i][1]*scale, acc[i][2]*scale, acc[i][3]*scale);
    }
}

// ---------------- softmax ----------------------------------------------------------
__global__ void __launch_bounds__(256) k_softmax()
{
    __shared__ float sbuf[8];
    const size_t row = blockIdx.x;
    float* p = g_s + row * SEQ_L;
    const int c0 = threadIdx.x * 4;
    float4 v = *(const float4*)(p + c0);
    float mx = fmaxf(fmaxf(v.x, v.y), fmaxf(v.z, v.w));
    mx = blk_max8(mx, sbuf);
    float e0 = __expf(v.x - mx), e1 = __expf(v.y - mx);
    float e2 = __expf(v.z - mx), e3 = __expf(v.w - mx);
    float s = blk_sum8(e0 + e1 + e2 + e3, sbuf);
    const float inv = 1.0f / s;
    *(float4*)(p + c0) = make_float4(e0*inv, e1*inv, e2*inv, e3*inv);
}

// ---------------- banded AV v2: 128(i) x 64(d) tile, 8x4 microtile ------------------
__global__ void __launch_bounds__(256) k_av()
{
    __shared__ float As[16][128];
    __shared__ float Vs[16][64];
    const int bh = blockIdx.z;
    const int i0 = blockIdx.y * 128;
    const int d0 = blockIdx.x * 64;
    const int tid = threadIdx.x, ty = tid >> 4, tx = tid & 15;

    const float* abase = g_s + (size_t)bh * SEQ_M * SEQ_L;
    const float* vbase = g_v + (size_t)bh * LT * DHEAD;

    const int ail = tid >> 1;          // 0..127
    const int ar8 = (tid & 1) * 8;     // rr base
    const float* arow_ptr = abase + (size_t)(i0 + ail) * SEQ_L;
    const int vr = tid >> 4, vd4 = (tid & 15) * 4;

    float acc[8][4] = {};
    for (int ch = 0; ch < (128 + SEQ_L) / 16; ch++) {   // 72 chunks
        const int ch16 = ch * 16;
        const int r0c = i0 + ch16;
#pragma unroll
        for (int u = 0; u < 8; u++) {
            const int rr = ar8 + u;
            const int j = ch16 + rr - ail;
            As[rr][ail] = (j >= 0 && j < SEQ_L) ? arow_ptr[j] : 0.0f;
        }
        *(float4*)&Vs[vr][vd4] =
            *(const float4*)(vbase + (size_t)(r0c + vr) * DHEAD + d0 + vd4);
        __syncthreads();
#pragma unroll
        for (int rr = 0; rr < 16; rr++) {
            float4 a0 = *(const float4*)&As[rr][ty*8];
            float4 a1 = *(const float4*)&As[rr][ty*8+4];
            float4 v4 = *(const float4*)&Vs[rr][tx*4];
            float a8[8] = {a0.x,a0.y,a0.z,a0.w,a1.x,a1.y,a1.z,a1.w};
            float vv[4] = {v4.x,v4.y,v4.z,v4.w};
#pragma unroll
            for (int i = 0; i < 8; i++)
#pragma unroll
                for (int j = 0; j < 4; j++)
                    acc[i][j] = fmaf(a8[i], vv[j], acc[i][j]);
        }
        __syncthreads();
    }
    const int b = bh >> 3, nh = bh & 7;
#pragma unroll
    for (int i = 0; i < 8; i++) {
        const int row = i0 + ty*8 + i;
        *(float4*)(g_ao + ((size_t)(b * SEQ_M + row)) * HDIM + nh * DHEAD + d0 + tx*4) =
            make_float4(acc[i][0], acc[i][1], acc[i][2], acc[i][3]);
    }
}

// ---------------- Wo projection + residual (tf32 tensor, proven) --------------------
__global__ void __launch_bounds__(256) k_wo(const float* __restrict__ Wo,
                                            const float* __restrict__ h)
{
    __shared__ float As[2][16][136];
    __shared__ float Bs[2][16][136];
    TF32_DECLS
    const int m0 = blockIdx.y * 128, n0 = blockIdx.x * 128;

    const float* aptr = g_ao + (size_t)(m0 + alm) * HDIM;
    const float* bptr = Wo + (size_t)blkr * HDIM + n0 + bln;

    float4 pa0 = *(const float4*)(aptr + alk);
    float4 pa1 = *(const float4*)(aptr + alk + 4);
    float4 pb0 = *(const float4*)(bptr);
    float4 pb1 = *(const float4*)(bptr + (size_t)8 * HDIM);
    TF32_STORE(0, pa0, pa1, pb0, pb1)
    __syncthreads();

    float acc[2][8][4] = {};
    const int NKB = HDIM / 16;
    for (int kb = 0; kb < NKB; kb++) {
        const int cur = kb & 1;
        if (kb + 1 < NKB) {
            pa0 = *(const float4*)(aptr + (kb+1)*16 + alk);
            pa1 = *(const float4*)(aptr + (kb+1)*16 + alk + 4);
            pb0 = *(const float4*)(bptr + (size_t)(kb+1)*16 * HDIM);
            pb1 = *(const float4*)(bptr + (size_t)((kb+1)*16 + 8) * HDIM);
        }
        TF32_COMPUTE(cur)
        if (kb + 1 < NKB) { TF32_STORE(cur ^ 1, pa0, pa1, pb0, pb1) }
        __syncthreads();
    }

#pragma unroll
    for (int mt = 0; mt < 2; mt++) {
        const int r0 = m0 + wm*32 + mt*16 + fg;
        const int r1 = r0 + 8;
#pragma unroll
        for (int nt = 0; nt < 8; nt++) {
            const int col = n0 + wn*64 + nt*8 + fc*2;
            float2 h0 = *(const float2*)(h + (size_t)r0 * HDIM + col);
            float2 h1 = *(const float2*)(h + (size_t)r1 * HDIM + col);
            *(float2*)(g_t1 + (size_t)r0 * HDIM + col) =
                make_float2(acc[mt][nt][0] + h0.x, acc[mt][nt][1] + h0.y);
            *(float2*)(g_t1 + (size_t)r1 * HDIM + col) =
                make_float2(acc[mt][nt][2] + h1.x, acc[mt][nt][3] + h1.y);
        }
    }
}

// ---------------- LN1 ---------------------------------------------------------------
__global__ void __launch_bounds__(256) k_ln1(const float* __restrict__ g,
                                             const float* __restrict__ b)
{
    __shared__ float sbuf[8];
    const int row = blockIdx.x;
    const int c0 = threadIdx.x * 4;
    float4 xv = *(const float4*)(g_t1 + (size_t)row * HDIM + c0);
    float s  = xv.x + xv.y + xv.z + xv.w;
    float s2 = xv.x*xv.x + xv.y*xv.y + xv.z*xv.z + xv.w*xv.w;
    s  = blk_sum8(s,  sbuf);
    s2 = blk_sum8(s2, sbuf);
    const float mu = s * (1.0f / HDIM);
    const float var = s2 * (1.0f / HDIM) - mu * mu;
    const float inv = rsqrtf(var + 1e-5f);
    float4 gv = *(const float4*)(g + c0);
    float4 bv = *(const float4*)(b + c0);
    *(float4*)(g_h1 + (size_t)row * HDIM + c0) = make_float4(
        (xv.x - mu) * inv * gv.x + bv.x,
        (xv.y - mu) * inv * gv.y + bv.y,
        (xv.z - mu) * inv * gv.z + bv.z,
        (xv.w - mu) * inv * gv.w + bv.w);
}

// ---------------- gating --------------------------------------------------------------
__global__ void __launch_bounds__(256) k_gate(const float* __restrict__ gw,
                                              const float* __restrict__ gb)
{
    __shared__ float lg[NEXP];
    const int t = blockIdx.x;
    const float* x = g_h1 + (size_t)t * HDIM;
    const int tid = threadIdx.x, w = tid >> 5, lane = tid & 31;
    float s = 0.0f;
    for (int hh = lane; hh < HDIM; hh += 32)
        s = fmaf(x[hh], gw[hh * NEXP + w], s);
#pragma unroll
    for (int o = 16; o; o >>= 1) s += __shfl_xor_sync(0xffffffffu, s, o);
    if (lane == 0) lg[w] = s + gb[w];
    __syncthreads();
    if (tid == 0) {
        int i0 = 0;
        for (int e = 1; e < NEXP; e++) if (lg[e] > lg[i0]) i0 = e;
        int i1 = -1;
        for (int e = 0; e < NEXP; e++) {
            if (e == i0) continue;
            if (i1 < 0 || lg[e] > lg[i1]) i1 = e;
        }
        const float e1 = __expf(lg[i1] - lg[i0]);
        const float den = 1.0f / (1.0f + e1);
        g_top_e[2*t]   = i0; g_top_e[2*t+1] = i1;
        g_top_w[2*t]   = den;
        g_top_w[2*t+1] = e1 * den;
        atomicAdd(&g_cnt[i0], 1);
        atomicAdd(&g_cnt[i1], 1);
    }
}

__global__ void k_scan()
{
    int s = 0;
    for (int e = 0; e < NEXP; e++) { g_off[e] = s; s += g_cnt[e]; }
}

__global__ void __launch_bounds__(256) k_scatter()
{
    const int t = blockIdx.x * 256 + threadIdx.x;
    if (t >= NTOK) return;
#pragma unroll
    for (int k = 0; k < 2; k++) {
        const int e = g_top_e[2*t + k];
        const int p = atomicAdd(&g_cur[e], 1);
        const int pos = g_off[e] + p;
        g_slot_token[pos] = t;
        g_slot_w[pos] = g_top_w[2*t + k];
        g_token_slot[2*t + k] = pos;
    }
}

// ---------------- MoE GEMM1 (tf32 tensor, proven) --------------------------------------
__global__ void __launch_bounds__(256) k_moe1(const float* __restrict__ w1,
                                              const float* __restrict__ b1)
{
    const int e = blockIdx.z;
    const int cnt = g_cnt[e];
    const int r0b = blockIdx.y * 128;
    if (r0b >= cnt) return;
    const int off = g_off[e];

    __shared__ float As[2][16][136];
    __shared__ float Bs[2][16][136];
    __shared__ int toks[128];
    TF32_DECLS
    const int n0 = blockIdx.x * 128;
    const float4 z4 = make_float4(0.f, 0.f, 0.f, 0.f);

    if (tid < 128) {
        const int r = r0b + tid;
        toks[tid] = (r < cnt) ? g_slot_token[off + r] : -1;
    }
    __syncthreads();
    const int tok = toks[alm];
    const bool aval = (tok >= 0);
    const float* aptr = g_h1 + (size_t)(aval ? tok : 0) * HDIM;
    const float* bptr = w1 + (size_t)e * HDIM * FDIM + (size_t)blkr * FDIM + n0 + bln;

    float4 pa0 = aval ? *(const float4*)(aptr + alk) : z4;
    float4 pa1 = aval ? *(const float4*)(aptr + alk + 4) : z4;
    float4 pb0 = *(const float4*)(bptr);
    float4 pb1 = *(const float4*)(bptr + (size_t)8 * FDIM);
    TF32_STORE(0, pa0, pa1, pb0, pb1)
    __syncthreads();

    float acc[2][8][4] = {};
    const int NKB = HDIM / 16;
    for (int kb = 0; kb < NKB; kb++) {
        const int cur = kb & 1;
        if (kb + 1 < NKB) {
            pa0 = aval ? *(const float4*)(aptr + (kb+1)*16 + alk) : z4;
            pa1 = aval ? *(const float4*)(aptr + (kb+1)*16 + alk + 4) : z4;
            pb0 = *(const float4*)(bptr + (size_t)(kb+1)*16 * FDIM);
            pb1 = *(const float4*)(bptr + (size_t)((kb+1)*16 + 8) * FDIM);
        }
        TF32_COMPUTE(cur)
        if (kb + 1 < NKB) { TF32_STORE(cur ^ 1, pa0, pa1, pb0, pb1) }
        __syncthreads();
    }

#pragma unroll
    for (int mt = 0; mt < 2; mt++) {
        const int r0 = r0b + wm*32 + mt*16 + fg;
        const int r1 = r0 + 8;
#pragma unroll
        for (int nt = 0; nt < 8; nt++) {
            const int col = n0 + wn*64 + nt*8 + fc*2;
            float2 bb = *(const float2*)(b1 + (size_t)e * FDIM + col);
            if (r0 < cnt)
                *(float2*)(g_hidden + (size_t)(off + r0) * FDIM + col) =
                    make_float2(fmaxf(acc[mt][nt][0] + bb.x, 0.f),
                                fmaxf(acc[mt][nt][1] + bb.y, 0.f));
            if (r1 < cnt)
                *(float2*)(g_hidden + (size_t)(off + r1) * FDIM + col) =
                    make_float2(fmaxf(acc[mt][nt][2] + bb.x, 0.f),
                                fmaxf(acc[mt][nt][3] + bb.y, 0.f));
        }
    }
}

// ---------------- MoE GEMM2 (tf32 tensor, proven) ----------------------------------------
__global__ void __launch_bounds__(256) k_moe2(const float* __restrict__ w2,
                                              const float* __restrict__ b2)
{
    const int e = blockIdx.z;
    const int cnt = g_cnt[e];
    const int r0b = blockIdx.y * 128;
    if (r0b >= cnt) return;
    const int off = g_off[e];

    __shared__ float As[2][16][136];
    __shared__ float Bs[2][16][136];
    TF32_DECLS
    const int n0 = blockIdx.x * 128;
    const float4 z4 = make_float4(0.f, 0.f, 0.f, 0.f);

    const int r = r0b + alm;
    const bool aval = (r < cnt);
    const float* aptr = g_hidden + (size_t)(off + (aval ? r : 0)) * FDIM;
    const float* bptr = w2 + (size_t)e * FDIM * HDIM + (size_t)blkr * HDIM + n0 + bln;

    float4 pa0 = aval ? *(const float4*)(aptr + alk) : z4;
    float4 pa1 = aval ? *(const float4*)(aptr + alk + 4) : z4;
    float4 pb0 = *(const float4*)(bptr);
    float4 pb1 = *(const float4*)(bptr + (size_t)8 * HDIM);
    TF32_STORE(0, pa0, pa1, pb0, pb1)
    __syncthreads();

    float acc[2][8][4] = {};
    const int NKB = FDIM / 16;
    for (int kb = 0; kb < NKB; kb++) {
        const int cur = kb & 1;
        if (kb + 1 < NKB) {
            pa0 = aval ? *(const float4*)(aptr + (kb+1)*16 + alk) : z4;
            pa1 = aval ? *(const float4*)(aptr + (kb+1)*16 + alk + 4) : z4;
            pb0 = *(const float4*)(bptr + (size_t)(kb+1)*16 * HDIM);
            pb1 = *(const float4*)(bptr + (size_t)((kb+1)*16 + 8) * HDIM);
        }
        TF32_COMPUTE(cur)
        if (kb + 1 < NKB) { TF32_STORE(cur ^ 1, pa0, pa1, pb0, pb1) }
        __syncthreads();
    }

#pragma unroll
    for (int mt = 0; mt < 2; mt++) {
        const int r0 = r0b + wm*32 + mt*16 + fg;
        const int r1 = r0 + 8;
#pragma unroll
        for (int nt = 0; nt < 8; nt++) {
            const int col = n0 + wn*64 + nt*8 + fc*2;
            float2 bb = *(const float2*)(b2 + (size_t)e * HDIM + col);
            if (r0 < cnt)
                *(float2*)(g_y + (size_t)(off + r0) * HDIM + col) =
                    make_float2(acc[mt][nt][0] + bb.x, acc[mt][nt][1] + bb.y);
            if (r1 < cnt)
                *(float2*)(g_y + (size_t)(off + r1) * HDIM + col) =
                    make_float2(acc[mt][nt][2] + bb.x, acc[mt][nt][3] + bb.y);
        }
    }
}

// ---------------- combine + LN2 -----------------------------------------------------------
__global__ void __launch_bounds__(256) k_combine(const float* __restrict__ mom_in,
                                                 const float* __restrict__ g,
                                                 const float* __restrict__ b,
                                                 float* __restrict__ out)
{
    __shared__ float sbuf[8];
    const int t = blockIdx.x;
    const int s0 = g_token_slot[2*t], s1 = g_token_slot[2*t + 1];
    const float w0 = g_slot_w[s0], w1 = g_slot_w[s1];
    const int c0 = threadIdx.x * 4;

    float4 h1v = *(const float4*)(g_h1 + (size_t)t * HDIM + c0);
    float4 mv  = *(const float4*)(mom_in + (size_t)t * HDIM + c0);
    float4 y0  = *(const float4*)(g_y + (size_t)s0 * HDIM + c0);
    float4 y1  = *(const float4*)(g_y + (size_t)s1 * HDIM + c0);

    float momn[4], x[4];
    momn[0] = 0.7f*mv.x + w0*y0.x + w1*y1.x;
    momn[1] = 0.7f*mv.y + w0*y0.y + w1*y1.y;
    momn[2] = 0.7f*mv.z + w0*y0.z + w1*y1.z;
    momn[3] = 0.7f*mv.w + w0*y0.w + w1*y1.w;
    x[0] = h1v.x - momn[0]; x[1] = h1v.y - momn[1];
    x[2] = h1v.z - momn[2]; x[3] = h1v.w - momn[3];

    float s  = x[0] + x[1] + x[2] + x[3];
    float s2 = x[0]*x[0] + x[1]*x[1] + x[2]*x[2] + x[3]*x[3];
    s  = blk_sum8(s,  sbuf);
    s2 = blk_sum8(s2, sbuf);
    const float mu = s * (1.0f / HDIM);
    const float var = s2 * (1.0f / HDIM) - mu * mu;
    const float inv = rsqrtf(var + 1e-5f);
    float4 gv = *(const float4*)(g + c0);
    float4 bv = *(const float4*)(b + c0);

    *(float4*)(out + (size_t)t * HDIM + c0) = make_float4(
        (x[0] - mu) * inv * gv.x + bv.x,
        (x[1] - mu) * inv * gv.y + bv.y,
        (x[2] - mu) * inv * gv.z + bv.z,
        (x[3] - mu) * inv * gv.w + bv.w);
    *(float4*)(out + (size_t)NTOK * HDIM + (size_t)t * HDIM + c0) =
        make_float4(momn[0], momn[1], momn[2], momn[3]);
}

// ---------------- launch ---------------------------------------------------------------------
extern "C" void kernel_launch(void* const* d_in, const int* in_sizes, int n_in,
                              void* d_out, int out_size)
{
    const float* h       = (const float*)d_in[0];
    const float* h_cache = (const float*)d_in[1];
    const float* pos     = (const float*)d_in[2];
    const float* mom     = (const float*)d_in[3];
    const float* Wq      = (const float*)d_in[4];
    const float* Wk      = (const float*)d_in[5];
    const float* Wv      = (const float*)d_in[6];
    const float* Wo      = (const float*)d_in[7];
    const float* gate_w  = (const float*)d_in[8];
    const float* gate_b  = (const float*)d_in[9];
    const float* w1      = (const float*)d_in[10];
    const float* b1      = (const float*)d_in[11];
    const float* w2      = (const float*)d_in[12];
    const float* b2      = (const float*)d_in[13];
    const float* ln1g    = (const float*)d_in[14];
    const float* ln1b    = (const float*)d_in[15];
    const float* ln2g    = (const float*)d_in[16];
    const float* ln2b    = (const float*)d_in[17];
    float* out = (float*)d_out;

    k_init<<<1, 32>>>();
    k_proj<0><<<dim3(HDIM/128, NTOK/128), 256>>>(h, h_cache, Wq);
    k_proj<1><<<dim3(HDIM/128, (BATCH*LT)/128), 256>>>(h, h_cache, Wk);
    k_proj<2><<<dim3(HDIM/128, (BATCH*LT)/128), 256>>>(h, h_cache, Wv);
    k_scores<<<dim3(SEQ_L/64, SEQ_M/128, NBH), 256>>>(pos);
    k_softmax<<<NBH*SEQ_M, 256>>>();
    k_av<<<dim3(DHEAD/64, SEQ_M/128, NBH), 256>>>();
    k_wo<<<dim3(HDIM/128, NTOK/128), 256>>>(Wo, h);
    k_ln1<<<NTOK, 256>>>(ln1g, ln1b);
    k_gate<<<NTOK, 256>>>(gate_w, gate_b);
    k_scan<<<1, 1>>>();
    k_scatter<<<NTOK/256, 256>>>();
    k_moe1<<<dim3(FDIM/128, NSLOT/128, NEXP), 256>>>(w1, b1);
    k_moe2<<<dim3(HDIM/128, NSLOT/128, NEXP), 256>>>(w2, b2);
    k_combine<<<NTOK, 256>>>(mom, ln2g, ln2b, out);
}

// round 12
// speedup vs baseline: 1.5609x; 1.0251x over previous
#include <cuda_runtime.h>
#include <math.h>

#define BATCH 4
#define SEQ_M 1024
#define HDIM  1024
#define NHEAD 8
#define DHEAD 128
#define SEQ_L 1024
#define NEXP  8
#define FDIM  4096
#define NTOK  (BATCH*SEQ_M)
#define NBH   (BATCH*NHEAD)
#define LT    (SEQ_L+SEQ_M)
#define NSLOT (NTOK*2)

// ---------------- scratch (device globals) -------------------------------------
__device__ float g_q[(size_t)NBH*SEQ_M*DHEAD];
__device__ float g_k[(size_t)NBH*LT*DHEAD];
__device__ float g_v[(size_t)NBH*LT*DHEAD];
__device__ float g_s[(size_t)NBH*SEQ_M*SEQ_L];
__device__ float g_ao[(size_t)NTOK*HDIM];
__device__ float g_t1[(size_t)NTOK*HDIM];
__device__ float g_h1[(size_t)NTOK*HDIM];
__device__ float g_hidden[(size_t)NSLOT*FDIM];
__device__ float g_y[(size_t)NSLOT*HDIM];
__device__ int   g_cnt[NEXP];
__device__ int   g_cur[NEXP];
__device__ int   g_off[NEXP];
__device__ int   g_slot_token[NSLOT];
__device__ float g_slot_w[NSLOT];
__device__ int   g_token_slot[NTOK*2];
__device__ int   g_top_e[NTOK*2];
__device__ float g_top_w[NTOK*2];

// ---------------- tf32 helpers -----------------------------------------------
__device__ __forceinline__ unsigned f2tf(float x)
{
    unsigned y;
    asm("cvt.rna.tf32.f32 %0, %1;" : "=r"(y) : "f"(x));
    return y;
}
__device__ __forceinline__ float4 tf4(float4 v)
{
    return make_float4(__uint_as_float(f2tf(v.x)), __uint_as_float(f2tf(v.y)),
                       __uint_as_float(f2tf(v.z)), __uint_as_float(f2tf(v.w)));
}

#define MMA_TF32(d0,d1,d2,d3,a0,a1,a2,a3,b0,b1)                             \
    asm volatile("mma.sync.aligned.m16n8k8.row.col.f32.tf32.tf32.f32 "      \
        "{%0,%1,%2,%3}, {%4,%5,%6,%7}, {%8,%9}, {%0,%1,%2,%3};"             \
        : "+f"(d0),"+f"(d1),"+f"(d2),"+f"(d3)                               \
        : "r"(a0),"r"(a1),"r"(a2),"r"(a3),"r"(b0),"r"(b1));

// ---------------- tf32 128x128x32 GEMM (deep kblock, phase-split prefetch) ------
// 256 threads = 8 warps (4x2); warp tile 32(M) x 64(N); mma m16n8k8.
// Dynamic smem: A[2][32][136] + B[2][32][136] floats = 69632 bytes.
// A stored transposed [k][m]; fragment LDS provably conflict-free (136 % 32 == 8).
#define G32_SMEM_BYTES 69632

#define G32_DECLS                                                            \
    const int tid = threadIdx.x, lane = tid & 31, warp = tid >> 5;           \
    const int wm = warp >> 1, wn = warp & 1;                                 \
    const int fg = lane >> 2, fc = lane & 3;                                 \
    const int alm = tid & 127, kslot = (tid >> 7) * 16;                      \
    const int blkr = tid >> 5, bln = lane * 4;                               \
    extern __shared__ float smp[];                                           \
    const float4 z4 = make_float4(0.f, 0.f, 0.f, 0.f);                       \
    (void)z4;

#define AS(buf,k,m) smp[(buf)*4352 + (k)*136 + (m)]
#define BS(buf,k,n) smp[8704 + (buf)*4352 + (k)*136 + (n)]

#define G32_STA(buf, kbase, P0, P1) {                                        \
    const float* _q0 = (const float*)&(P0);                                  \
    const float* _q1 = (const float*)&(P1);                                  \
    _Pragma("unroll")                                                        \
    for (int i = 0; i < 4; i++) {                                            \
        AS(buf, (kbase)+i,   alm) = __uint_as_float(f2tf(_q0[i]));           \
        AS(buf, (kbase)+4+i, alm) = __uint_as_float(f2tf(_q1[i]));           \
    } }

#define G32_COMP8(cur, k8) {                                                 \
    unsigned afr[2][4], bfr[8][2];                                           \
    _Pragma("unroll")                                                        \
    for (int mt = 0; mt < 2; mt++) {                                         \
        const int mr = wm*32 + mt*16 + fg;                                   \
        afr[mt][0] = __float_as_uint(AS(cur, (k8)+fc,   mr));                \
        afr[mt][1] = __float_as_uint(AS(cur, (k8)+fc,   mr+8));              \
        afr[mt][2] = __float_as_uint(AS(cur, (k8)+fc+4, mr));                \
        afr[mt][3] = __float_as_uint(AS(cur, (k8)+fc+4, mr+8));              \
    }                                                                        \
    _Pragma("unroll")                                                        \
    for (int nt = 0; nt < 8; nt++) {                                         \
        const int nc = wn*64 + nt*8 + fg;                                    \
        bfr[nt][0] = __float_as_uint(BS(cur, (k8)+fc,   nc));                \
        bfr[nt][1] = __float_as_uint(BS(cur, (k8)+fc+4, nc));                \
    }                                                                        \
    _Pragma("unroll")                                                        \
    for (int mt = 0; mt < 2; mt++)                                           \
    _Pragma("unroll")                                                        \
    for (int nt = 0; nt < 8; nt++)                                           \
        MMA_TF32(acc[mt][nt][0],acc[mt][nt][1],acc[mt][nt][2],acc[mt][nt][3],\
                 afr[mt][0],afr[mt][1],afr[mt][2],afr[mt][3],                \
                 bfr[nt][0],bfr[nt][1]); }

// Prologue: fill buffer 0 with chunk 0 (both phases), then sync.
#define G32_PROLOGUE(LDB, AVALID) {                                          \
    float4 a0 = z4, a1 = z4;                                                 \
    if (AVALID) { a0 = *(const float4*)(aptr + kslot);                       \
                  a1 = *(const float4*)(aptr + kslot + 4); }                 \
    float4 b0 = *(const float4*)(bptr + (size_t)blkr * (LDB));               \
    float4 b1 = *(const float4*)(bptr + (size_t)(blkr + 8) * (LDB));         \
    G32_STA(0, kslot, a0, a1)                                                \
    *(float4*)&BS(0, blkr,   bln) = tf4(b0);                                 \
    *(float4*)&BS(0, blkr+8, bln) = tf4(b1);                                 \
    if (AVALID) { a0 = *(const float4*)(aptr + kslot + 8);                   \
                  a1 = *(const float4*)(aptr + kslot + 12); }                \
    b0 = *(const float4*)(bptr + (size_t)(blkr + 16) * (LDB));               \
    b1 = *(const float4*)(bptr + (size_t)(blkr + 24) * (LDB));               \
    G32_STA(0, kslot + 8, a0, a1)                                            \
    *(float4*)&BS(0, blkr+16, bln) = tf4(b0);                                \
    *(float4*)&BS(0, blkr+24, bln) = tf4(b1);                                \
    }                                                                        \
    __syncthreads();

// Main loop over 32-deep chunks; two-phase register staging keeps liveness low.
#define G32_LOOP(NKB, LDB, AVALID)                                           \
    float acc[2][8][4] = {};                                                 \
    for (int kb = 0; kb < (NKB); kb++) {                                     \
        const int cur = kb & 1;                                              \
        const bool pf = (kb + 1 < (NKB));                                    \
        float4 a0 = z4, a1 = z4, b0 = z4, b1 = z4;                           \
        if (pf) {                                                            \
            if (AVALID) {                                                    \
                a0 = *(const float4*)(aptr + (kb+1)*32 + kslot);             \
                a1 = *(const float4*)(aptr + (kb+1)*32 + kslot + 4);         \
            }                                                                \
            b0 = *(const float4*)(bptr + (size_t)((kb+1)*32 + blkr)*(LDB));  \
            b1 = *(const float4*)(bptr + (size_t)((kb+1)*32 + blkr+8)*(LDB));\
        }                                                                    \
        G32_COMP8(cur, 0)                                                    \
        G32_COMP8(cur, 8)                                                    \
        if (pf) {                                                            \
            const int nxt = cur ^ 1;                                         \
            G32_STA(nxt, kslot, a0, a1)                                      \
            *(float4*)&BS(nxt, blkr,   bln) = tf4(b0);                       \
            *(float4*)&BS(nxt, blkr+8, bln) = tf4(b1);                       \
            if (AVALID) {                                                    \
                a0 = *(const float4*)(aptr + (kb+1)*32 + kslot + 8);         \
                a1 = *(const float4*)(aptr + (kb+1)*32 + kslot + 12);        \
            }                                                                \
            b0 = *(const float4*)(bptr + (size_t)((kb+1)*32 + blkr+16)*(LDB));\
            b1 = *(const float4*)(bptr + (size_t)((kb+1)*32 + blkr+24)*(LDB));\
        }                                                                    \
        G32_COMP8(cur, 16)                                                   \
        G32_COMP8(cur, 24)                                                   \
        if (pf) {                                                            \
            const int nxt = cur ^ 1;                                         \
            G32_STA(nxt, kslot + 8, a0, a1)                                  \
            *(float4*)&BS(nxt, blkr+16, bln) = tf4(b0);                      \
            *(float4*)&BS(nxt, blkr+24, bln) = tf4(b1);                      \
        }                                                                    \
        __syncthreads();                                                     \
    }

// ---------------- block reductions (256 threads / 8 warps) --------------------
__device__ __forceinline__ float blk_sum8(float v, float* sbuf)
{
    const int lane = threadIdx.x & 31, w = threadIdx.x >> 5;
#pragma unroll
    for (int o = 16; o; o >>= 1) v += __shfl_xor_sync(0xffffffffu, v, o);
    __syncthreads();
    if (lane == 0) sbuf[w] = v;
    __syncthreads();
    return sbuf[0]+sbuf[1]+sbuf[2]+sbuf[3]+sbuf[4]+sbuf[5]+sbuf[6]+sbuf[7];
}

__device__ __forceinline__ float blk_max8(float v, float* sbuf)
{
    const int lane = threadIdx.x & 31, w = threadIdx.x >> 5;
#pragma unroll
    for (int o = 16; o; o >>= 1) v = fmaxf(v, __shfl_xor_sync(0xffffffffu, v, o));
    __syncthreads();
    if (lane == 0) sbuf[w] = v;
    __syncthreads();
    return fmaxf(fmaxf(fmaxf(sbuf[0],sbuf[1]),fmaxf(sbuf[2],sbuf[3])),
                 fmaxf(fmaxf(sbuf[4],sbuf[5]),fmaxf(sbuf[6],sbuf[7])));
}

// ---------------- init ----------------------------------------------------------
__global__ void k_init()
{
    int t = threadIdx.x;
    if (t < NEXP) { g_cnt[t] = 0; g_cur[t] = 0; }
}

// ---------------- QKV projections (tf32 tensor, deep-k) ---------------------------
template<int WHICH>
__global__ void __launch_bounds__(256) k_proj(
    const float* __restrict__ h, const float* __restrict__ h_cache,
    const float* __restrict__ W)
{
    G32_DECLS
    const int m0 = blockIdx.y * 128, n0 = blockIdx.x * 128;

    const int arow = m0 + alm;
    const float* aptr;
    if (WHICH == 0) {
        aptr = h + (size_t)arow * HDIM;
    } else {
        const int b = arow >> 11, t = arow & 2047;
        aptr = (t < SEQ_L) ? (h_cache + ((size_t)b * SEQ_L + t) * HDIM)
                           : (h + ((size_t)b * SEQ_M + (t - SEQ_L)) * HDIM);
    }
    const float* bptr = W + n0 + bln;

    G32_PROLOGUE(HDIM, true)
    G32_LOOP(HDIM/32, HDIM, true)

#pragma unroll
    for (int mt = 0; mt < 2; mt++) {
        const int r0 = m0 + wm*32 + mt*16 + fg;
        const int r1 = r0 + 8;
#pragma unroll
        for (int nt = 0; nt < 8; nt++) {
            const int col = n0 + wn*64 + nt*8 + fc*2;
            const int nh = col >> 7, d = col & 127;
            float *o0, *o1;
            if (WHICH == 0) {
                int b = r0 >> 10, mm = r0 & 1023;
                o0 = g_q + (((size_t)(b*NHEAD + nh) * SEQ_M + mm) * DHEAD + d);
                b = r1 >> 10; mm = r1 & 1023;
                o1 = g_q + (((size_t)(b*NHEAD + nh) * SEQ_M + mm) * DHEAD + d);
            } else {
                float* base = (WHICH == 1) ? g_k : g_v;
                int b = r0 >> 11, t = r0 & 2047;
                o0 = base + (((size_t)(b*NHEAD + nh) * LT + t) * DHEAD + d);
                b = r1 >> 11; t = r1 & 2047;
                o1 = base + (((size_t)(b*NHEAD + nh) * LT + t) * DHEAD + d);
            }
            *(float2*)o0 = make_float2(acc[mt][nt][0], acc[mt][nt][1]);
            *(float2*)o1 = make_float2(acc[mt][nt][2], acc[mt][nt][3]);
        }
    }
}

// ---------------- banded scores v2 (proven R11) -------------------------------------
__global__ void __launch_bounds__(256) k_scores(const float* __restrict__ pos)
{
    __shared__ float Qs[16][128];
    __shared__ float Ks[16][192];
    __shared__ float Ps[16][64];
    const int bh = blockIdx.z;
    const int i0 = blockIdx.y * 128, j0 = blockIdx.x * 64;
    const int tid = threadIdx.x, ty = tid >> 4, tx = tid & 15;

    const float* qbase = g_q + (size_t)bh * SEQ_M * DHEAD;
    const float* kbase = g_k + (size_t)bh * LT * DHEAD;

    const int qi = tid >> 1, qk = (tid & 1) * 8;
    const int pk = tid >> 4, pj = (tid & 15) * 4;
    const int kr = tid >> 1, kk8 = (tid & 1) * 8;

    float acc[8][4] = {};
    for (int dc = 0; dc < DHEAD; dc += 16) {
        float4 q0 = *(const float4*)(qbase + (size_t)(i0+qi)*DHEAD + dc + qk);
        float4 q1 = *(const float4*)(qbase + (size_t)(i0+qi)*DHEAD + dc + qk + 4);
        Qs[qk+0][qi]=q0.x; Qs[qk+1][qi]=q0.y; Qs[qk+2][qi]=q0.z; Qs[qk+3][qi]=q0.w;
        Qs[qk+4][qi]=q1.x; Qs[qk+5][qi]=q1.y; Qs[qk+6][qi]=q1.z; Qs[qk+7][qi]=q1.w;

        float4 k0 = *(const float4*)(kbase + (size_t)(i0+j0+kr)*DHEAD + dc + kk8);
        float4 k1 = *(const float4*)(kbase + (size_t)(i0+j0+kr)*DHEAD + dc + kk8 + 4);
        Ks[kk8+0][kr]=k0.x; Ks[kk8+1][kr]=k0.y; Ks[kk8+2][kr]=k0.z; Ks[kk8+3][kr]=k0.w;
        Ks[kk8+4][kr]=k1.x; Ks[kk8+5][kr]=k1.y; Ks[kk8+6][kr]=k1.z; Ks[kk8+7][kr]=k1.w;
        if (tid < 128) {
            const int kr2 = 128 + (tid >> 1);
            const int kb2 = (tid & 1) * 8;
            float4 m0v = *(const float4*)(kbase + (size_t)(i0+j0+kr2)*DHEAD + dc + kb2);
            float4 m1v = *(const float4*)(kbase + (size_t)(i0+j0+kr2)*DHEAD + dc + kb2 + 4);
            Ks[kb2+0][kr2]=m0v.x; Ks[kb2+1][kr2]=m0v.y; Ks[kb2+2][kr2]=m0v.z; Ks[kb2+3][kr2]=m0v.w;
            Ks[kb2+4][kr2]=m1v.x; Ks[kb2+5][kr2]=m1v.y; Ks[kb2+6][kr2]=m1v.z; Ks[kb2+7][kr2]=m1v.w;
        }
        *(float4*)&Ps[pk][pj] = *(const float4*)(pos + (size_t)(dc + pk) * SEQ_L + j0 + pj);
        __syncthreads();

        const int base = ty*8 + tx*4;
#pragma unroll
        for (int kk = 0; kk < 16; kk++) {
            float4 a0 = *(const float4*)&Qs[kk][ty*8];
            float4 a1 = *(const float4*)&Qs[kk][ty*8+4];
            float4 p4 = *(const float4*)&Ps[kk][tx*4];
            float4 kA = *(const float4*)&Ks[kk][base];
            float4 kB = *(const float4*)&Ks[kk][base+4];
            float4 kC = *(const float4*)&Ks[kk][base+8];
            float q8[8] = {a0.x,a0.y,a0.z,a0.w,a1.x,a1.y,a1.z,a1.w};
            float pr[4] = {p4.x,p4.y,p4.z,p4.w};
            float kv[12] = {kA.x,kA.y,kA.z,kA.w,kB.x,kB.y,kB.z,kB.w,
                            kC.x,kC.y,kC.z,kC.w};
#pragma unroll
            for (int i = 0; i < 8; i++)
#pragma unroll
                for (int j = 0; j < 4; j++)
                    acc[i][j] = fmaf(q8[i], kv[i+j] + pr[j], acc[i][j]);
        }
        __syncthreads();
    }
    const float scale = 1.0f / 32.0f;
#pragma unroll
    for (int i = 0; i < 8; i++) {
        const int row = i0 + ty*8 + i;
        *(float4*)(g_s + ((size_t)bh * SEQ_M + row) * SEQ_L + j0 + tx*4) =
            make_float4(acc[i][0]*scale, acc[i][1]*scale, acc[i][2]*scale, acc[i][3]*scale);
    }
}

// ---------------- softmax ----------------------------------------------------------
__global__ void __launch_bounds__(256) k_softmax()
{
    __shared__ float sbuf[8];
    const size_t row = blockIdx.x;
    float* p = g_s + row * SEQ_L;
    const int c0 = threadIdx.x * 4;
    float4 v = *(const float4*)(p + c0);
    float mx = fmaxf(fmaxf(v.x, v.y), fmaxf(v.z, v.w));
    mx = blk_max8(mx, sbuf);
    float e0 = __expf(v.x - mx), e1 = __expf(v.y - mx);
    float e2 = __expf(v.z - mx), e3 = __expf(v.w - mx);
    float s = blk_sum8(e0 + e1 + e2 + e3, sbuf);
    const float inv = 1.0f / s;
    *(float4*)(p + c0) = make_float4(e0*inv, e1*inv, e2*inv, e3*inv);
}

// ---------------- banded AV v2 (proven R11) -------------------------------------------
__global__ void __launch_bounds__(256) k_av()
{
    __shared__ float As2[16][128];
    __shared__ float Vs[16][64];
    const int bh = blockIdx.z;
    const int i0 = blockIdx.y * 128;
    const int d0 = blockIdx.x * 64;
    const int tid = threadIdx.x, ty = tid >> 4, tx = tid & 15;

    const float* abase = g_s + (size_t)bh * SEQ_M * SEQ_L;
    const float* vbase = g_v + (size_t)bh * LT * DHEAD;

    const int ail = tid >> 1;
    const int ar8 = (tid & 1) * 8;
    const float* arow_ptr = abase + (size_t)(i0 + ail) * SEQ_L;
    const int vr = tid >> 4, vd4 = (tid & 15) * 4;

    float acc[8][4] = {};
    for (int ch = 0; ch < (128 + SEQ_L) / 16; ch++) {
        const int ch16 = ch * 16;
        const int r0c = i0 + ch16;
#pragma unroll
        for (int u = 0; u < 8; u++) {
            const int rr = ar8 + u;
            const int j = ch16 + rr - ail;
            As2[rr][ail] = (j >= 0 && j < SEQ_L) ? arow_ptr[j] : 0.0f;
        }
        *(float4*)&Vs[vr][vd4] =
            *(const float4*)(vbase + (size_t)(r0c + vr) * DHEAD + d0 + vd4);
        __syncthreads();
#pragma unroll
        for (int rr = 0; rr < 16; rr++) {
            float4 a0 = *(const float4*)&As2[rr][ty*8];
            float4 a1 = *(const float4*)&As2[rr][ty*8+4];
            float4 v4 = *(const float4*)&Vs[rr][tx*4];
            float a8[8] = {a0.x,a0.y,a0.z,a0.w,a1.x,a1.y,a1.z,a1.w};
            float vv[4] = {v4.x,v4.y,v4.z,v4.w};
#pragma unroll
            for (int i = 0; i < 8; i++)
#pragma unroll
                for (int j = 0; j < 4; j++)
                    acc[i][j] = fmaf(a8[i], vv[j], acc[i][j]);
        }
        __syncthreads();
    }
    const int b = bh >> 3, nh = bh & 7;
#pragma unroll
    for (int i = 0; i < 8; i++) {
        const int row = i0 + ty*8 + i;
        *(float4*)(g_ao + ((size_t)(b * SEQ_M + row)) * HDIM + nh * DHEAD + d0 + tx*4) =
            make_float4(acc[i][0], acc[i][1], acc[i][2], acc[i][3]);
    }
}

// ---------------- Wo projection + residual (tf32 tensor, deep-k) ----------------------
__global__ void __launch_bounds__(256) k_wo(const float* __restrict__ Wo,
                                            const float* __restrict__ h)
{
    G32_DECLS
    const int m0 = blockIdx.y * 128, n0 = blockIdx.x * 128;

    const float* aptr = g_ao + (size_t)(m0 + alm) * HDIM;
    const float* bptr = Wo + n0 + bln;

    G32_PROLOGUE(HDIM, true)
    G32_LOOP(HDIM/32, HDIM, true)

#pragma unroll
    for (int mt = 0; mt < 2; mt++) {
        const int r0 = m0 + wm*32 + mt*16 + fg;
        const int r1 = r0 + 8;
#pragma unroll
        for (int nt = 0; nt < 8; nt++) {
            const int col = n0 + wn*64 + nt*8 + fc*2;
            float2 h0 = *(const float2*)(h + (size_t)r0 * HDIM + col);
            float2 h1 = *(const float2*)(h + (size_t)r1 * HDIM + col);
            *(float2*)(g_t1 + (size_t)r0 * HDIM + col) =
                make_float2(acc[mt][nt][0] + h0.x, acc[mt][nt][1] + h0.y);
            *(float2*)(g_t1 + (size_t)r1 * HDIM + col) =
                make_float2(acc[mt][nt][2] + h1.x, acc[mt][nt][3] + h1.y);
        }
    }
}

// ---------------- LN1 ---------------------------------------------------------------
__global__ void __launch_bounds__(256) k_ln1(const float* __restrict__ g,
                                             const float* __restrict__ b)
{
    __shared__ float sbuf[8];
    const int row = blockIdx.x;
    const int c0 = threadIdx.x * 4;
    float4 xv = *(const float4*)(g_t1 + (size_t)row * HDIM + c0);
    float s  = xv.x + xv.y + xv.z + xv.w;
    float s2 = xv.x*xv.x + xv.y*xv.y + xv.z*xv.z + xv.w*xv.w;
    s  = blk_sum8(s,  sbuf);
    s2 = blk_sum8(s2, sbuf);
    const float mu = s * (1.0f / HDIM);
    const float var = s2 * (1.0f / HDIM) - mu * mu;
    const float inv = rsqrtf(var + 1e-5f);
    float4 gv = *(const float4*)(g + c0);
    float4 bv = *(const float4*)(b + c0);
    *(float4*)(g_h1 + (size_t)row * HDIM + c0) = make_float4(
        (xv.x - mu) * inv * gv.x + bv.x,
        (xv.y - mu) * inv * gv.y + bv.y,
        (xv.z - mu) * inv * gv.z + bv.z,
        (xv.w - mu) * inv * gv.w + bv.w);
}

// ---------------- gating --------------------------------------------------------------
__global__ void __launch_bounds__(256) k_gate(const float* __restrict__ gw,
                                              const float* __restrict__ gb)
{
    __shared__ float lg[NEXP];
    const int t = blockIdx.x;
    const float* x = g_h1 + (size_t)t * HDIM;
    const int tid = threadIdx.x, w = tid >> 5, lane = tid & 31;
    float s = 0.0f;
    for (int hh = lane; hh < HDIM; hh += 32)
        s = fmaf(x[hh], gw[hh * NEXP + w], s);
#pragma unroll
    for (int o = 16; o; o >>= 1) s += __shfl_xor_sync(0xffffffffu, s, o);
    if (lane == 0) lg[w] = s + gb[w];
    __syncthreads();
    if (tid == 0) {
        int i0 = 0;
        for (int e = 1; e < NEXP; e++) if (lg[e] > lg[i0]) i0 = e;
        int i1 = -1;
        for (int e = 0; e < NEXP; e++) {
            if (e == i0) continue;
            if (i1 < 0 || lg[e] > lg[i1]) i1 = e;
        }
        const float e1 = __expf(lg[i1] - lg[i0]);
        const float den = 1.0f / (1.0f + e1);
        g_top_e[2*t]   = i0; g_top_e[2*t+1] = i1;
        g_top_w[2*t]   = den;
        g_top_w[2*t+1] = e1 * den;
        atomicAdd(&g_cnt[i0], 1);
        atomicAdd(&g_cnt[i1], 1);
    }
}

__global__ void k_scan()
{
    int s = 0;
    for (int e = 0; e < NEXP; e++) { g_off[e] = s; s += g_cnt[e]; }
}

__global__ void __launch_bounds__(256) k_scatter()
{
    const int t = blockIdx.x * 256 + threadIdx.x;
    if (t >= NTOK) return;
#pragma unroll
    for (int k = 0; k < 2; k++) {
        const int e = g_top_e[2*t + k];
        const int p = atomicAdd(&g_cur[e], 1);
        const int pos = g_off[e] + p;
        g_slot_token[pos] = t;
        g_slot_w[pos] = g_top_w[2*t + k];
        g_token_slot[2*t + k] = pos;
    }
}

// ---------------- MoE GEMM1 (tf32 tensor, deep-k) ----------------------------------------
__global__ void __launch_bounds__(256) k_moe1(const float* __restrict__ w1,
                                              const float* __restrict__ b1)
{
    const int e = blockIdx.z;
    const int cnt = g_cnt[e];
    const int r0b = blockIdx.y * 128;
    if (r0b >= cnt) return;
    const int off = g_off[e];

    __shared__ int toks[128];
    G32_DECLS
    const int n0 = blockIdx.x * 128;

    if (tid < 128) {
        const int r = r0b + tid;
        toks[tid] = (r < cnt) ? g_slot_token[off + r] : -1;
    }
    __syncthreads();
    const int tok = toks[alm];
    const bool aval = (tok >= 0);
    const float* aptr = g_h1 + (size_t)(aval ? tok : 0) * HDIM;
    const float* bptr = w1 + (size_t)e * HDIM * FDIM + n0 + bln;

    G32_PROLOGUE(FDIM, aval)
    G32_LOOP(HDIM/32, FDIM, aval)

#pragma unroll
    for (int mt = 0; mt < 2; mt++) {
        const int r0 = r0b + wm*32 + mt*16 + fg;
        const int r1 = r0 + 8;
#pragma unroll
        for (int nt = 0; nt < 8; nt++) {
            const int col = n0 + wn*64 + nt*8 + fc*2;
            float2 bb = *(const float2*)(b1 + (size_t)e * FDIM + col);
            if (r0 < cnt)
                *(float2*)(g_hidden + (size_t)(off + r0) * FDIM + col) =
                    make_float2(fmaxf(acc[mt][nt][0] + bb.x, 0.f),
                                fmaxf(acc[mt][nt][1] + bb.y, 0.f));
            if (r1 < cnt)
                *(float2*)(g_hidden + (size_t)(off + r1) * FDIM + col) =
                    make_float2(fmaxf(acc[mt][nt][2] + bb.x, 0.f),
                                fmaxf(acc[mt][nt][3] + bb.y, 0.f));
        }
    }
}

// ---------------- MoE GEMM2 (tf32 tensor, deep-k) ------------------------------------------
__global__ void __launch_bounds__(256) k_moe2(const float* __restrict__ w2,
                                              const float* __restrict__ b2)
{
    const int e = blockIdx.z;
    const int cnt = g_cnt[e];
    const int r0b = blockIdx.y * 128;
    if (r0b >= cnt) return;
    const int off = g_off[e];

    G32_DECLS
    const int n0 = blockIdx.x * 128;

    const int r = r0b + alm;
    const bool aval = (r < cnt);
    const float* aptr = g_hidden + (size_t)(off + (aval ? r : 0)) * FDIM;
    const float* bptr = w2 + (size_t)e * FDIM * HDIM + n0 + bln;

    G32_PROLOGUE(HDIM, aval)
    G32_LOOP(FDIM/32, HDIM, aval)

#pragma unroll
    for (int mt = 0; mt < 2; mt++) {
        const int r0 = r0b + wm*32 + mt*16 + fg;
        const int r1 = r0 + 8;
#pragma unroll
        for (int nt = 0; nt < 8; nt++) {
            const int col = n0 + wn*64 + nt*8 + fc*2;
            float2 bb = *(const float2*)(b2 + (size_t)e * HDIM + col);
            if (r0 < cnt)
                *(float2*)(g_y + (size_t)(off + r0) * HDIM + col) =
                    make_float2(acc[mt][nt][0] + bb.x, acc[mt][nt][1] + bb.y);
            if (r1 < cnt)
                *(float2*)(g_y + (size_t)(off + r1) * HDIM + col) =
                    make_float2(acc[mt][nt][2] + bb.x, acc[mt][nt][3] + bb.y);
        }
    }
}

// ---------------- combine + LN2 -----------------------------------------------------------
__global__ void __launch_bounds__(256) k_combine(const float* __restrict__ mom_in,
                                                 const float* __restrict__ g,
                                                 const float* __restrict__ b,
                                                 float* __restrict__ out)
{
    __shared__ float sbuf[8];
    const int t = blockIdx.x;
    const int s0 = g_token_slot[2*t], s1 = g_token_slot[2*t + 1];
    const float w0 = g_slot_w[s0], w1 = g_slot_w[s1];
    const int c0 = threadIdx.x * 4;

    float4 h1v = *(const float4*)(g_h1 + (size_t)t * HDIM + c0);
    float4 mv  = *(const float4*)(mom_in + (size_t)t * HDIM + c0);
    float4 y0  = *(const float4*)(g_y + (size_t)s0 * HDIM + c0);
    float4 y1  = *(const float4*)(g_y + (size_t)s1 * HDIM + c0);

    float momn[4], x[4];
    momn[0] = 0.7f*mv.x + w0*y0.x + w1*y1.x;
    momn[1] = 0.7f*mv.y + w0*y0.y + w1*y1.y;
    momn[2] = 0.7f*mv.z + w0*y0.z + w1*y1.z;
    momn[3] = 0.7f*mv.w + w0*y0.w + w1*y1.w;
    x[0] = h1v.x - momn[0]; x[1] = h1v.y - momn[1];
    x[2] = h1v.z - momn[2]; x[3] = h1v.w - momn[3];

    float s  = x[0] + x[1] + x[2] + x[3];
    float s2 = x[0]*x[0] + x[1]*x[1] + x[2]*x[2] + x[3]*x[3];
    s  = blk_sum8(s,  sbuf);
    s2 = blk_sum8(s2, sbuf);
    const float mu = s * (1.0f / HDIM);
    const float var = s2 * (1.0f / HDIM) - mu * mu;
    const float inv = rsqrtf(var + 1e-5f);
    float4 gv = *(const float4*)(g + c0);
    float4 bv = *(const float4*)(b + c0);

    *(float4*)(out + (size_t)t * HDIM + c0) = make_float4(
        (x[0] - mu) * inv * gv.x + bv.x,
        (x[1] - mu) * inv * gv.y + bv.y,
        (x[2] - mu) * inv * gv.z + bv.z,
        (x[3] - mu) * inv * gv.w + bv.w);
    *(float4*)(out + (size_t)NTOK * HDIM + (size_t)t * HDIM + c0) =
        make_float4(momn[0], momn[1], momn[2], momn[3]);
}

// ---------------- launch ---------------------------------------------------------------------
extern "C" void kernel_launch(void* const* d_in, const int* in_sizes, int n_in,
                              void* d_out, int out_size)
{
    const float* h       = (const float*)d_in[0];
    const float* h_cache = (const float*)d_in[1];
    const float* pos     = (const float*)d_in[2];
    const float* mom     = (const float*)d_in[3];
    const float* Wq      = (const float*)d_in[4];
    const float* Wk      = (const float*)d_in[5];
    const float* Wv      = (const float*)d_in[6];
    const float* Wo      = (const float*)d_in[7];
    const float* gate_w  = (const float*)d_in[8];
    const float* gate_b  = (const float*)d_in[9];
    const float* w1      = (const float*)d_in[10];
    const float* b1      = (const float*)d_in[11];
    const float* w2      = (const float*)d_in[12];
    const float* b2      = (const float*)d_in[13];
    const float* ln1g    = (const float*)d_in[14];
    const float* ln1b    = (const float*)d_in[15];
    const float* ln2g    = (const float*)d_in[16];
    const float* ln2b    = (const float*)d_in[17];
    float* out = (float*)d_out;

    cudaFuncSetAttribute(k_proj<0>, cudaFuncAttributeMaxDynamicSharedMemorySize, G32_SMEM_BYTES);
    cudaFuncSetAttribute(k_proj<1>, cudaFuncAttributeMaxDynamicSharedMemorySize, G32_SMEM_BYTES);
    cudaFuncSetAttribute(k_proj<2>, cudaFuncAttributeMaxDynamicSharedMemorySize, G32_SMEM_BYTES);
    cudaFuncSetAttribute(k_wo,      cudaFuncAttributeMaxDynamicSharedMemorySize, G32_SMEM_BYTES);
    cudaFuncSetAttribute(k_moe1,    cudaFuncAttributeMaxDynamicSharedMemorySize, G32_SMEM_BYTES);
    cudaFuncSetAttribute(k_moe2,    cudaFuncAttributeMaxDynamicSharedMemorySize, G32_SMEM_BYTES);

    k_init<<<1, 32>>>();
    k_proj<0><<<dim3(HDIM/128, NTOK/128), 256, G32_SMEM_BYTES>>>(h, h_cache, Wq);
    k_proj<1><<<dim3(HDIM/128, (BATCH*LT)/128), 256, G32_SMEM_BYTES>>>(h, h_cache, Wk);
    k_proj<2><<<dim3(HDIM/128, (BATCH*LT)/128), 256, G32_SMEM_BYTES>>>(h, h_cache, Wv);
    k_scores<<<dim3(SEQ_L/64, SEQ_M/128, NBH), 256>>>(pos);
    k_softmax<<<NBH*SEQ_M, 256>>>();
    k_av<<<dim3(DHEAD/64, SEQ_M/128, NBH), 256>>>();
    k_wo<<<dim3(HDIM/128, NTOK/128), 256, G32_SMEM_BYTES>>>(Wo, h);
    k_ln1<<<NTOK, 256>>>(ln1g, ln1b);
    k_gate<<<NTOK, 256>>>(gate_w, gate_b);
    k_scan<<<1, 1>>>();
    k_scatter<<<NTOK/256, 256>>>();
    k_moe1<<<dim3(FDIM/128, NSLOT/128, NEXP), 256, G32_SMEM_BYTES>>>(w1, b1);
    k_moe2<<<dim3(HDIM/128, NSLOT/128, NEXP), 256, G32_SMEM_BYTES>>>(w2, b2);
    k_combine<<<NTOK, 256>>>(mom, ln2g, ln2b, out);
}

// round 13
// speedup vs baseline: 1.6222x; 1.0392x over previous
#include <cuda_runtime.h>
#include <math.h>

#define BATCH 4
#define SEQ_M 1024
#define HDIM  1024
#define NHEAD 8
#define DHEAD 128
#define SEQ_L 1024
#define NEXP  8
#define FDIM  4096
#define NTOK  (BATCH*SEQ_M)
#define NBH   (BATCH*NHEAD)
#define LT    (SEQ_L+SEQ_M)
#define NSLOT (NTOK*2)

// ---------------- scratch (device globals) -------------------------------------
__device__ float g_q[(size_t)NBH*SEQ_M*DHEAD];
__device__ float g_k[(size_t)NBH*LT*DHEAD];
__device__ float g_v[(size_t)NBH*LT*DHEAD];
__device__ float g_s[(size_t)NBH*SEQ_M*SEQ_L];
__device__ float g_ao[(size_t)NTOK*HDIM];
__device__ float g_t1[(size_t)NTOK*HDIM];
__device__ float g_h1[(size_t)NTOK*HDIM];
__device__ float g_hidden[(size_t)NSLOT*FDIM];
__device__ float g_y[(size_t)NSLOT*HDIM];
__device__ int   g_cnt[NEXP];
__device__ int   g_cur[NEXP];
__device__ int   g_off[NEXP];
__device__ int   g_slot_token[NSLOT];
__device__ float g_slot_w[NSLOT];
__device__ int   g_token_slot[NTOK*2];
__device__ int   g_top_e[NTOK*2];
__device__ float g_top_w[NTOK*2];

// ---------------- tf32 helpers -----------------------------------------------
__device__ __forceinline__ unsigned f2tf(float x)
{
    unsigned y;
    asm("cvt.rna.tf32.f32 %0, %1;" : "=r"(y) : "f"(x));
    return y;
}
__device__ __forceinline__ float4 tf4(float4 v)
{
    return make_float4(__uint_as_float(f2tf(v.x)), __uint_as_float(f2tf(v.y)),
                       __uint_as_float(f2tf(v.z)), __uint_as_float(f2tf(v.w)));
}

#define MMA_TF32(d0,d1,d2,d3,a0,a1,a2,a3,b0,b1)                             \
    asm volatile("mma.sync.aligned.m16n8k8.row.col.f32.tf32.tf32.f32 "      \
        "{%0,%1,%2,%3}, {%4,%5,%6,%7}, {%8,%9}, {%0,%1,%2,%3};"             \
        : "+f"(d0),"+f"(d1),"+f"(d2),"+f"(d3)                               \
        : "r"(a0),"r"(a1),"r"(a2),"r"(a3),"r"(b0),"r"(b1));

// ---------------- tf32 128x128x32 GEMM (deep kblock, phase-split prefetch) ------
#define G32_SMEM_BYTES 69632

#define G32_DECLS                                                            \
    const int tid = threadIdx.x, lane = tid & 31, warp = tid >> 5;           \
    const int wm = warp >> 1, wn = warp & 1;                                 \
    const int fg = lane >> 2, fc = lane & 3;                                 \
    const int alm = tid & 127, kslot = (tid >> 7) * 16;                      \
    const int blkr = tid >> 5, bln = lane * 4;                               \
    extern __shared__ float smp[];                                           \
    const float4 z4 = make_float4(0.f, 0.f, 0.f, 0.f);                       \
    (void)z4;

#define AS(buf,k,m) smp[(buf)*4352 + (k)*136 + (m)]
#define BS(buf,k,n) smp[8704 + (buf)*4352 + (k)*136 + (n)]

#define G32_STA(buf, kbase, P0, P1) {                                        \
    const float* _q0 = (const float*)&(P0);                                  \
    const float* _q1 = (const float*)&(P1);                                  \
    _Pragma("unroll")                                                        \
    for (int i = 0; i < 4; i++) {                                            \
        AS(buf, (kbase)+i,   alm) = __uint_as_float(f2tf(_q0[i]));           \
        AS(buf, (kbase)+4+i, alm) = __uint_as_float(f2tf(_q1[i]));           \
    } }

#define G32_COMP8(cur, k8) {                                                 \
    unsigned afr[2][4], bfr[8][2];                                           \
    _Pragma("unroll")                                                        \
    for (int mt = 0; mt < 2; mt++) {                                         \
        const int mr = wm*32 + mt*16 + fg;                                   \
        afr[mt][0] = __float_as_uint(AS(cur, (k8)+fc,   mr));                \
        afr[mt][1] = __float_as_uint(AS(cur, (k8)+fc,   mr+8));              \
        afr[mt][2] = __float_as_uint(AS(cur, (k8)+fc+4, mr));                \
        afr[mt][3] = __float_as_uint(AS(cur, (k8)+fc+4, mr+8));              \
    }                                                                        \
    _Pragma("unroll")                                                        \
    for (int nt = 0; nt < 8; nt++) {                                         \
        const int nc = wn*64 + nt*8 + fg;                                    \
        bfr[nt][0] = __float_as_uint(BS(cur, (k8)+fc,   nc));                \
        bfr[nt][1] = __float_as_uint(BS(cur, (k8)+fc+4, nc));                \
    }                                                                        \
    _Pragma("unroll")                                                        \
    for (int mt = 0; mt < 2; mt++)                                           \
    _Pragma("unroll")                                                        \
    for (int nt = 0; nt < 8; nt++)                                           \
        MMA_TF32(acc[mt][nt][0],acc[mt][nt][1],acc[mt][nt][2],acc[mt][nt][3],\
                 afr[mt][0],afr[mt][1],afr[mt][2],afr[mt][3],                \
                 bfr[nt][0],bfr[nt][1]); }

#define G32_PROLOGUE(LDB, AVALID) {                                          \
    float4 a0 = z4, a1 = z4;                                                 \
    if (AVALID) { a0 = *(const float4*)(aptr + kslot);                       \
                  a1 = *(const float4*)(aptr + kslot + 4); }                 \
    float4 b0 = *(const float4*)(bptr + (size_t)blkr * (LDB));               \
    float4 b1 = *(const float4*)(bptr + (size_t)(blkr + 8) * (LDB));         \
    G32_STA(0, kslot, a0, a1)                                                \
    *(float4*)&BS(0, blkr,   bln) = tf4(b0);                                 \
    *(float4*)&BS(0, blkr+8, bln) = tf4(b1);                                 \
    if (AVALID) { a0 = *(const float4*)(aptr + kslot + 8);                   \
                  a1 = *(const float4*)(aptr + kslot + 12); }                \
    b0 = *(const float4*)(bptr + (size_t)(blkr + 16) * (LDB));               \
    b1 = *(const float4*)(bptr + (size_t)(blkr + 24) * (LDB));               \
    G32_STA(0, kslot + 8, a0, a1)                                            \
    *(float4*)&BS(0, blkr+16, bln) = tf4(b0);                                \
    *(float4*)&BS(0, blkr+24, bln) = tf4(b1);                                \
    }                                                                        \
    __syncthreads();

#define G32_LOOP(NKB, LDB, AVALID)                                           \
    float acc[2][8][4] = {};                                                 \
    for (int kb = 0; kb < (NKB); kb++) {                                     \
        const int cur = kb & 1;                                              \
        const bool pf = (kb + 1 < (NKB));                                    \
        float4 a0 = z4, a1 = z4, b0 = z4, b1 = z4;                           \
        if (pf) {                                                            \
            if (AVALID) {                                                    \
                a0 = *(const float4*)(aptr + (kb+1)*32 + kslot);             \
                a1 = *(const float4*)(aptr + (kb+1)*32 + kslot + 4);         \
            }                                                                \
            b0 = *(const float4*)(bptr + (size_t)((kb+1)*32 + blkr)*(LDB));  \
            b1 = *(const float4*)(bptr + (size_t)((kb+1)*32 + blkr+8)*(LDB));\
        }                                                                    \
        G32_COMP8(cur, 0)                                                    \
        G32_COMP8(cur, 8)                                                    \
        if (pf) {                                                            \
            const int nxt = cur ^ 1;                                         \
            G32_STA(nxt, kslot, a0, a1)                                      \
            *(float4*)&BS(nxt, blkr,   bln) = tf4(b0);                       \
            *(float4*)&BS(nxt, blkr+8, bln) = tf4(b1);                       \
            if (AVALID) {                                                    \
                a0 = *(const float4*)(aptr + (kb+1)*32 + kslot + 8);         \
                a1 = *(const float4*)(aptr + (kb+1)*32 + kslot + 12);        \
            }                                                                \
            b0 = *(const float4*)(bptr + (size_t)((kb+1)*32 + blkr+16)*(LDB));\
            b1 = *(const float4*)(bptr + (size_t)((kb+1)*32 + blkr+24)*(LDB));\
        }                                                                    \
        G32_COMP8(cur, 16)                                                   \
        G32_COMP8(cur, 24)                                                   \
        if (pf) {                                                            \
            const int nxt = cur ^ 1;                                         \
            G32_STA(nxt, kslot + 8, a0, a1)                                  \
            *(float4*)&BS(nxt, blkr+16, bln) = tf4(b0);                      \
            *(float4*)&BS(nxt, blkr+24, bln) = tf4(b1);                      \
        }                                                                    \
        __syncthreads();                                                     \
    }

// ---------------- block reductions (256 threads / 8 warps) --------------------
__device__ __forceinline__ float blk_sum8(float v, float* sbuf)
{
    const int lane = threadIdx.x & 31, w = threadIdx.x >> 5;
#pragma unroll
    for (int o = 16; o; o >>= 1) v += __shfl_xor_sync(0xffffffffu, v, o);
    __syncthreads();
    if (lane == 0) sbuf[w] = v;
    __syncthreads();
    return sbuf[0]+sbuf[1]+sbuf[2]+sbuf[3]+sbuf[4]+sbuf[5]+sbuf[6]+sbuf[7];
}

__device__ __forceinline__ float blk_max8(float v, float* sbuf)
{
    const int lane = threadIdx.x & 31, w = threadIdx.x >> 5;
#pragma unroll
    for (int o = 16; o; o >>= 1) v = fmaxf(v, __shfl_xor_sync(0xffffffffu, v, o));
    __syncthreads();
    if (lane == 0) sbuf[w] = v;
    __syncthreads();
    return fmaxf(fmaxf(fmaxf(sbuf[0],sbuf[1]),fmaxf(sbuf[2],sbuf[3])),
                 fmaxf(fmaxf(sbuf[4],sbuf[5]),fmaxf(sbuf[6],sbuf[7])));
}

// ---------------- init ----------------------------------------------------------
__global__ void k_init()
{
    int t = threadIdx.x;
    if (t < NEXP) { g_cnt[t] = 0; g_cur[t] = 0; }
}

// ---------------- fused QKV projections (one launch, tail-filled) -----------------
// blocks 0..255: Q (32 mb x 8 nb); 256..767: K (64 x 8); 768..1279: V (64 x 8).
__global__ void __launch_bounds__(256) k_qkv(
    const float* __restrict__ h, const float* __restrict__ h_cache,
    const float* __restrict__ Wq, const float* __restrict__ Wk,
    const float* __restrict__ Wv)
{
    G32_DECLS
    const int bid = blockIdx.x;
    int job, mb, nb;
    if (bid < 256)      { job = 0; mb = bid >> 3;          nb = bid & 7; }
    else if (bid < 768) { job = 1; mb = (bid - 256) >> 3;  nb = bid & 7; }
    else                { job = 2; mb = (bid - 768) >> 3;  nb = bid & 7; }
    const int m0 = mb * 128, n0 = nb * 128;
    const float* W = (job == 0) ? Wq : (job == 1) ? Wk : Wv;

    const int arow = m0 + alm;
    const float* aptr;
    if (job == 0) {
        aptr = h + (size_t)arow * HDIM;
    } else {
        const int b = arow >> 11, t = arow & 2047;
        aptr = (t < SEQ_L) ? (h_cache + ((size_t)b * SEQ_L + t) * HDIM)
                           : (h + ((size_t)b * SEQ_M + (t - SEQ_L)) * HDIM);
    }
    const float* bptr = W + n0 + bln;

    G32_PROLOGUE(HDIM, true)
    G32_LOOP(HDIM/32, HDIM, true)

#pragma unroll
    for (int mt = 0; mt < 2; mt++) {
        const int r0 = m0 + wm*32 + mt*16 + fg;
        const int r1 = r0 + 8;
#pragma unroll
        for (int nt = 0; nt < 8; nt++) {
            const int col = n0 + wn*64 + nt*8 + fc*2;
            const int nh = col >> 7, d = col & 127;
            float *o0, *o1;
            if (job == 0) {
                int b = r0 >> 10, mm = r0 & 1023;
                o0 = g_q + (((size_t)(b*NHEAD + nh) * SEQ_M + mm) * DHEAD + d);
                b = r1 >> 10; mm = r1 & 1023;
                o1 = g_q + (((size_t)(b*NHEAD + nh) * SEQ_M + mm) * DHEAD + d);
            } else {
                float* base = (job == 1) ? g_k : g_v;
                int b = r0 >> 11, t = r0 & 2047;
                o0 = base + (((size_t)(b*NHEAD + nh) * LT + t) * DHEAD + d);
                b = r1 >> 11; t = r1 & 2047;
                o1 = base + (((size_t)(b*NHEAD + nh) * LT + t) * DHEAD + d);
            }
            *(float2*)o0 = make_float2(acc[mt][nt][0], acc[mt][nt][1]);
            *(float2*)o1 = make_float2(acc[mt][nt][2], acc[mt][nt][3]);
        }
    }
}

// ---------------- banded scores v2 (proven R11) -------------------------------------
__global__ void __launch_bounds__(256) k_scores(const float* __restrict__ pos)
{
    __shared__ float Qs[16][128];
    __shared__ float Ks[16][192];
    __shared__ float Ps[16][64];
    const int bh = blockIdx.z;
    const int i0 = blockIdx.y * 128, j0 = blockIdx.x * 64;
    const int tid = threadIdx.x, ty = tid >> 4, tx = tid & 15;

    const float* qbase = g_q + (size_t)bh * SEQ_M * DHEAD;
    const float* kbase = g_k + (size_t)bh * LT * DHEAD;

    const int qi = tid >> 1, qk = (tid & 1) * 8;
    const int pk = tid >> 4, pj = (tid & 15) * 4;
    const int kr = tid >> 1, kk8 = (tid & 1) * 8;

    float acc[8][4] = {};
    for (int dc = 0; dc < DHEAD; dc += 16) {
        float4 q0 = *(const float4*)(qbase + (size_t)(i0+qi)*DHEAD + dc + qk);
        float4 q1 = *(const float4*)(qbase + (size_t)(i0+qi)*DHEAD + dc + qk + 4);
        Qs[qk+0][qi]=q0.x; Qs[qk+1][qi]=q0.y; Qs[qk+2][qi]=q0.z; Qs[qk+3][qi]=q0.w;
        Qs[qk+4][qi]=q1.x; Qs[qk+5][qi]=q1.y; Qs[qk+6][qi]=q1.z; Qs[qk+7][qi]=q1.w;

        float4 k0 = *(const float4*)(kbase + (size_t)(i0+j0+kr)*DHEAD + dc + kk8);
        float4 k1 = *(const float4*)(kbase + (size_t)(i0+j0+kr)*DHEAD + dc + kk8 + 4);
        Ks[kk8+0][kr]=k0.x; Ks[kk8+1][kr]=k0.y; Ks[kk8+2][kr]=k0.z; Ks[kk8+3][kr]=k0.w;
        Ks[kk8+4][kr]=k1.x; Ks[kk8+5][kr]=k1.y; Ks[kk8+6][kr]=k1.z; Ks[kk8+7][kr]=k1.w;
        if (tid < 128) {
            const int kr2 = 128 + (tid >> 1);
            const int kb2 = (tid & 1) * 8;
            float4 m0v = *(const float4*)(kbase + (size_t)(i0+j0+kr2)*DHEAD + dc + kb2);
            float4 m1v = *(const float4*)(kbase + (size_t)(i0+j0+kr2)*DHEAD + dc + kb2 + 4);
            Ks[kb2+0][kr2]=m0v.x; Ks[kb2+1][kr2]=m0v.y; Ks[kb2+2][kr2]=m0v.z; Ks[kb2+3][kr2]=m0v.w;
            Ks[kb2+4][kr2]=m1v.x; Ks[kb2+5][kr2]=m1v.y; Ks[kb2+6][kr2]=m1v.z; Ks[kb2+7][kr2]=m1v.w;
        }
        *(float4*)&Ps[pk][pj] = *(const float4*)(pos + (size_t)(dc + pk) * SEQ_L + j0 + pj);
        __syncthreads();

        const int base = ty*8 + tx*4;
#pragma unroll
        for (int kk = 0; kk < 16; kk++) {
            float4 a0 = *(const float4*)&Qs[kk][ty*8];
            float4 a1 = *(const float4*)&Qs[kk][ty*8+4];
            float4 p4 = *(const float4*)&Ps[kk][tx*4];
            float4 kA = *(const float4*)&Ks[kk][base];
            float4 kB = *(const float4*)&Ks[kk][base+4];
            float4 kC = *(const float4*)&Ks[kk][base+8];
            float q8[8] = {a0.x,a0.y,a0.z,a0.w,a1.x,a1.y,a1.z,a1.w};
            float pr[4] = {p4.x,p4.y,p4.z,p4.w};
            float kv[12] = {kA.x,kA.y,kA.z,kA.w,kB.x,kB.y,kB.z,kB.w,
                            kC.x,kC.y,kC.z,kC.w};
#pragma unroll
            for (int i = 0; i < 8; i++)
#pragma unroll
                for (int j = 0; j < 4; j++)
                    acc[i][j] = fmaf(q8[i], kv[i+j] + pr[j], acc[i][j]);
        }
        __syncthreads();
    }
    const float scale = 1.0f / 32.0f;
#pragma unroll
    for (int i = 0; i < 8; i++) {
        const int row = i0 + ty*8 + i;
        *(float4*)(g_s + ((size_t)bh * SEQ_M + row) * SEQ_L + j0 + tx*4) =
            make_float4(acc[i][0]*scale, acc[i][1]*scale, acc[i][2]*scale, acc[i][3]*scale);
    }
}

// ---------------- softmax ----------------------------------------------------------
__global__ void __launch_bounds__(256) k_softmax()
{
    __shared__ float sbuf[8];
    const size_t row = blockIdx.x;
    float* p = g_s + row * SEQ_L;
    const int c0 = threadIdx.x * 4;
    float4 v = *(const float4*)(p + c0);
    float mx = fmaxf(fmaxf(v.x, v.y), fmaxf(v.z, v.w));
    mx = blk_max8(mx, sbuf);
    float e0 = __expf(v.x - mx), e1 = __expf(v.y - mx);
    float e2 = __expf(v.z - mx), e3 = __expf(v.w - mx);
    float s = blk_sum8(e0 + e1 + e2 + e3, sbuf);
    const float inv = 1.0f / s;
    *(float4*)(p + c0) = make_float4(e0*inv, e1*inv, e2*inv, e3*inv);
}

// ---------------- banded AV v2 (proven R11) -------------------------------------------
__global__ void __launch_bounds__(256) k_av()
{
    __shared__ float As2[16][128];
    __shared__ float Vs[16][64];
    const int bh = blockIdx.z;
    const int i0 = blockIdx.y * 128;
    const int d0 = blockIdx.x * 64;
    const int tid = threadIdx.x, ty = tid >> 4, tx = tid & 15;

    const float* abase = g_s + (size_t)bh * SEQ_M * SEQ_L;
    const float* vbase = g_v + (size_t)bh * LT * DHEAD;

    const int ail = tid >> 1;
    const int ar8 = (tid & 1) * 8;
    const float* arow_ptr = abase + (size_t)(i0 + ail) * SEQ_L;
    const int vr = tid >> 4, vd4 = (tid & 15) * 4;

    float acc[8][4] = {};
    for (int ch = 0; ch < (128 + SEQ_L) / 16; ch++) {
        const int ch16 = ch * 16;
        const int r0c = i0 + ch16;
#pragma unroll
        for (int u = 0; u < 8; u++) {
            const int rr = ar8 + u;
            const int j = ch16 + rr - ail;
            As2[rr][ail] = (j >= 0 && j < SEQ_L) ? arow_ptr[j] : 0.0f;
        }
        *(float4*)&Vs[vr][vd4] =
            *(const float4*)(vbase + (size_t)(r0c + vr) * DHEAD + d0 + vd4);
        __syncthreads();
#pragma unroll
        for (int rr = 0; rr < 16; rr++) {
            float4 a0 = *(const float4*)&As2[rr][ty*8];
            float4 a1 = *(const float4*)&As2[rr][ty*8+4];
            float4 v4 = *(const float4*)&Vs[rr][tx*4];
            float a8[8] = {a0.x,a0.y,a0.z,a0.w,a1.x,a1.y,a1.z,a1.w};
            float vv[4] = {v4.x,v4.y,v4.z,v4.w};
#pragma unroll
            for (int i = 0; i < 8; i++)
#pragma unroll
                for (int j = 0; j < 4; j++)
                    acc[i][j] = fmaf(a8[i], vv[j], acc[i][j]);
        }
        __syncthreads();
    }
    const int b = bh >> 3, nh = bh & 7;
#pragma unroll
    for (int i = 0; i < 8; i++) {
        const int row = i0 + ty*8 + i;
        *(float4*)(g_ao + ((size_t)(b * SEQ_M + row)) * HDIM + nh * DHEAD + d0 + tx*4) =
            make_float4(acc[i][0], acc[i][1], acc[i][2], acc[i][3]);
    }
}

// ---------------- Wo projection + residual (tf32 tensor, deep-k) ----------------------
__global__ void __launch_bounds__(256) k_wo(const float* __restrict__ Wo,
                                            const float* __restrict__ h)
{
    G32_DECLS
    const int m0 = blockIdx.y * 128, n0 = blockIdx.x * 128;

    const float* aptr = g_ao + (size_t)(m0 + alm) * HDIM;
    const float* bptr = Wo + n0 + bln;

    G32_PROLOGUE(HDIM, true)
    G32_LOOP(HDIM/32, HDIM, true)

#pragma unroll
    for (int mt = 0; mt < 2; mt++) {
        const int r0 = m0 + wm*32 + mt*16 + fg;
        const int r1 = r0 + 8;
#pragma unroll
        for (int nt = 0; nt < 8; nt++) {
            const int col = n0 + wn*64 + nt*8 + fc*2;
            float2 h0 = *(const float2*)(h + (size_t)r0 * HDIM + col);
            float2 h1 = *(const float2*)(h + (size_t)r1 * HDIM + col);
            *(float2*)(g_t1 + (size_t)r0 * HDIM + col) =
                make_float2(acc[mt][nt][0] + h0.x, acc[mt][nt][1] + h0.y);
            *(float2*)(g_t1 + (size_t)r1 * HDIM + col) =
                make_float2(acc[mt][nt][2] + h1.x, acc[mt][nt][3] + h1.y);
        }
    }
}

// ---------------- fused LN1 + gate ------------------------------------------------------
__global__ void __launch_bounds__(256) k_ln1gate(
    const float* __restrict__ g, const float* __restrict__ b,
    const float* __restrict__ gw, const float* __restrict__ gb)
{
    __shared__ float sbuf[8];
    __shared__ float xs[HDIM];
    __shared__ float lg[NEXP];
    const int row = blockIdx.x;
    const int c0 = threadIdx.x * 4;
    float4 xv = *(const float4*)(g_t1 + (size_t)row * HDIM + c0);
    float s  = xv.x + xv.y + xv.z + xv.w;
    float s2 = xv.x*xv.x + xv.y*xv.y + xv.z*xv.z + xv.w*xv.w;
    s  = blk_sum8(s,  sbuf);
    s2 = blk_sum8(s2, sbuf);
    const float mu = s * (1.0f / HDIM);
    const float var = s2 * (1.0f / HDIM) - mu * mu;
    const float inv = rsqrtf(var + 1e-5f);
    float4 gv = *(const float4*)(g + c0);
    float4 bv = *(const float4*)(b + c0);
    float4 r = make_float4(
        (xv.x - mu) * inv * gv.x + bv.x,
        (xv.y - mu) * inv * gv.y + bv.y,
        (xv.z - mu) * inv * gv.z + bv.z,
        (xv.w - mu) * inv * gv.w + bv.w);
    *(float4*)(g_h1 + (size_t)row * HDIM + c0) = r;
    *(float4*)&xs[c0] = r;
    __syncthreads();

    const int w = threadIdx.x >> 5, lane = threadIdx.x & 31;
    float sg = 0.0f;
    for (int hh = lane; hh < HDIM; hh += 32)
        sg = fmaf(xs[hh], gw[hh * NEXP + w], sg);
#pragma unroll
    for (int o = 16; o; o >>= 1) sg += __shfl_xor_sync(0xffffffffu, sg, o);
    if (lane == 0) lg[w] = sg + gb[w];
    __syncthreads();
    if (threadIdx.x == 0) {
        int i0 = 0;
        for (int e = 1; e < NEXP; e++) if (lg[e] > lg[i0]) i0 = e;
        int i1 = -1;
        for (int e = 0; e < NEXP; e++) {
            if (e == i0) continue;
            if (i1 < 0 || lg[e] > lg[i1]) i1 = e;
        }
        const float e1 = __expf(lg[i1] - lg[i0]);
        const float den = 1.0f / (1.0f + e1);
        g_top_e[2*row]   = i0; g_top_e[2*row+1] = i1;
        g_top_w[2*row]   = den;
        g_top_w[2*row+1] = e1 * den;
        atomicAdd(&g_cnt[i0], 1);
        atomicAdd(&g_cnt[i1], 1);
    }
}

__global__ void k_scan()
{
    int s = 0;
    for (int e = 0; e < NEXP; e++) { g_off[e] = s; s += g_cnt[e]; }
}

__global__ void __launch_bounds__(256) k_scatter()
{
    const int t = blockIdx.x * 256 + threadIdx.x;
    if (t >= NTOK) return;
#pragma unroll
    for (int k = 0; k < 2; k++) {
        const int e = g_top_e[2*t + k];
        const int p = atomicAdd(&g_cur[e], 1);
        const int pos = g_off[e] + p;
        g_slot_token[pos] = t;
        g_slot_w[pos] = g_top_w[2*t + k];
        g_token_slot[2*t + k] = pos;
    }
}

// ---------------- MoE GEMM1 (tf32 tensor, deep-k) ----------------------------------------
__global__ void __launch_bounds__(256) k_moe1(const float* __restrict__ w1,
                                              const float* __restrict__ b1)
{
    const int e = blockIdx.z;
    const int cnt = g_cnt[e];
    const int r0b = blockIdx.y * 128;
    if (r0b >= cnt) return;
    const int off = g_off[e];

    __shared__ int toks[128];
    G32_DECLS
    const int n0 = blockIdx.x * 128;

    if (tid < 128) {
        const int r = r0b + tid;
        toks[tid] = (r < cnt) ? g_slot_token[off + r] : -1;
    }
    __syncthreads();
    const int tok = toks[alm];
    const bool aval = (tok >= 0);
    const float* aptr = g_h1 + (size_t)(aval ? tok : 0) * HDIM;
    const float* bptr = w1 + (size_t)e * HDIM * FDIM + n0 + bln;

    G32_PROLOGUE(FDIM, aval)
    G32_LOOP(HDIM/32, FDIM, aval)

#pragma unroll
    for (int mt = 0; mt < 2; mt++) {
        const int r0 = r0b + wm*32 + mt*16 + fg;
        const int r1 = r0 + 8;
#pragma unroll
        for (int nt = 0; nt < 8; nt++) {
            const int col = n0 + wn*64 + nt*8 + fc*2;
            float2 bb = *(const float2*)(b1 + (size_t)e * FDIM + col);
            if (r0 < cnt)
                *(float2*)(g_hidden + (size_t)(off + r0) * FDIM + col) =
                    make_float2(fmaxf(acc[mt][nt][0] + bb.x, 0.f),
                                fmaxf(acc[mt][nt][1] + bb.y, 0.f));
            if (r1 < cnt)
                *(float2*)(g_hidden + (size_t)(off + r1) * FDIM + col) =
                    make_float2(fmaxf(acc[mt][nt][2] + bb.x, 0.f),
                                fmaxf(acc[mt][nt][3] + bb.y, 0.f));
        }
    }
}

// ---------------- MoE GEMM2 (tf32 tensor, deep-k) ------------------------------------------
__global__ void __launch_bounds__(256) k_moe2(const float* __restrict__ w2,
                                              const float* __restrict__ b2)
{
    const int e = blockIdx.z;
    const int cnt = g_cnt[e];
    const int r0b = blockIdx.y * 128;
    if (r0b >= cnt) return;
    const int off = g_off[e];

    G32_DECLS
    const int n0 = blockIdx.x * 128;

    const int r = r0b + alm;
    const bool aval = (r < cnt);
    const float* aptr = g_hidden + (size_t)(off + (aval ? r : 0)) * FDIM;
    const float* bptr = w2 + (size_t)e * FDIM * HDIM + n0 + bln;

    G32_PROLOGUE(HDIM, aval)
    G32_LOOP(FDIM/32, HDIM, aval)

#pragma unroll
    for (int mt = 0; mt < 2; mt++) {
        const int r0 = r0b + wm*32 + mt*16 + fg;
        const int r1 = r0 + 8;
#pragma unroll
        for (int nt = 0; nt < 8; nt++) {
            const int col = n0 + wn*64 + nt*8 + fc*2;
            float2 bb = *(const float2*)(b2 + (size_t)e * HDIM + col);
            if (r0 < cnt)
                *(float2*)(g_y + (size_t)(off + r0) * HDIM + col) =
                    make_float2(acc[mt][nt][0] + bb.x, acc[mt][nt][1] + bb.y);
            if (r1 < cnt)
                *(float2*)(g_y + (size_t)(off + r1) * HDIM + col) =
                    make_float2(acc[mt][nt][2] + bb.x, acc[mt][nt][3] + bb.y);
        }
    }
}

// ---------------- combine + LN2 -----------------------------------------------------------
__global__ void __launch_bounds__(256) k_combine(const float* __restrict__ mom_in,
                                                 const float* __restrict__ g,
                                                 const float* __restrict__ b,
                                                 float* __restrict__ out)
{
    __shared__ float sbuf[8];
    const int t = blockIdx.x;
    const int s0 = g_token_slot[2*t], s1 = g_token_slot[2*t + 1];
    const float w0 = g_slot_w[s0], w1 = g_slot_w[s1];
    const int c0 = threadIdx.x * 4;

    float4 h1v = *(const float4*)(g_h1 + (size_t)t * HDIM + c0);
    float4 mv  = *(const float4*)(mom_in + (size_t)t * HDIM + c0);
    float4 y0  = *(const float4*)(g_y + (size_t)s0 * HDIM + c0);
    float4 y1  = *(const float4*)(g_y + (size_t)s1 * HDIM + c0);

    float momn[4], x[4];
    momn[0] = 0.7f*mv.x + w0*y0.x + w1*y1.x;
    momn[1] = 0.7f*mv.y + w0*y0.y + w1*y1.y;
    momn[2] = 0.7f*mv.z + w0*y0.z + w1*y1.z;
    momn[3] = 0.7f*mv.w + w0*y0.w + w1*y1.w;
    x[0] = h1v.x - momn[0]; x[1] = h1v.y - momn[1];
    x[2] = h1v.z - momn[2]; x[3] = h1v.w - momn[3];

    float s  = x[0] + x[1] + x[2] + x[3];
    float s2 = x[0]*x[0] + x[1]*x[1] + x[2]*x[2] + x[3]*x[3];
    s  = blk_sum8(s,  sbuf);
    s2 = blk_sum8(s2, sbuf);
    const float mu = s * (1.0f / HDIM);
    const float var = s2 * (1.0f / HDIM) - mu * mu;
    const float inv = rsqrtf(var + 1e-5f);
    float4 gv = *(const float4*)(g + c0);
    float4 bv = *(const float4*)(b + c0);

    *(float4*)(out + (size_t)t * HDIM + c0) = make_float4(
        (x[0] - mu) * inv * gv.x + bv.x,
        (x[1] - mu) * inv * gv.y + bv.y,
        (x[2] - mu) * inv * gv.z + bv.z,
        (x[3] - mu) * inv * gv.w + bv.w);
    *(float4*)(out + (size_t)NTOK * HDIM + (size_t)t * HDIM + c0) =
        make_float4(momn[0], momn[1], momn[2], momn[3]);
}

// ---------------- launch ---------------------------------------------------------------------
extern "C" void kernel_launch(void* const* d_in, const int* in_sizes, int n_in,
                              void* d_out, int out_size)
{
    const float* h       = (const float*)d_in[0];
    const float* h_cache = (const float*)d_in[1];
    const float* pos     = (const float*)d_in[2];
    const float* mom     = (const float*)d_in[3];
    const float* Wq      = (const float*)d_in[4];
    const float* Wk      = (const float*)d_in[5];
    const float* Wv      = (const float*)d_in[6];
    const float* Wo      = (const float*)d_in[7];
    const float* gate_w  = (const float*)d_in[8];
    const float* gate_b  = (const float*)d_in[9];
    const float* w1      = (const float*)d_in[10];
    const float* b1      = (const float*)d_in[11];
    const float* w2      = (const float*)d_in[12];
    const float* b2      = (const float*)d_in[13];
    const float* ln1g    = (const float*)d_in[14];
    const float* ln1b    = (const float*)d_in[15];
    const float* ln2g    = (const float*)d_in[16];
    const float* ln2b    = (const float*)d_in[17];
    float* out = (float*)d_out;

    cudaFuncSetAttribute(k_qkv,  cudaFuncAttributeMaxDynamicSharedMemorySize, G32_SMEM_BYTES);
    cudaFuncSetAttribute(k_wo,   cudaFuncAttributeMaxDynamicSharedMemorySize, G32_SMEM_BYTES);
    cudaFuncSetAttribute(k_moe1, cudaFuncAttributeMaxDynamicSharedMemorySize, G32_SMEM_BYTES);
    cudaFuncSetAttribute(k_moe2, cudaFuncAttributeMaxDynamicSharedMemorySize, G32_SMEM_BYTES);

    k_init<<<1, 32>>>();
    k_qkv<<<1280, 256, G32_SMEM_BYTES>>>(h, h_cache, Wq, Wk, Wv);
    k_scores<<<dim3(SEQ_L/64, SEQ_M/128, NBH), 256>>>(pos);
    k_softmax<<<NBH*SEQ_M, 256>>>();
    k_av<<<dim3(DHEAD/64, SEQ_M/128, NBH), 256>>>();
    k_wo<<<dim3(HDIM/128, NTOK/128), 256, G32_SMEM_BYTES>>>(Wo, h);
    k_ln1gate<<<NTOK, 256>>>(ln1g, ln1b, gate_w, gate_b);
    k_scan<<<1, 1>>>();
    k_scatter<<<NTOK/256, 256>>>();
    k_moe1<<<dim3(FDIM/128, NSLOT/128, NEXP), 256, G32_SMEM_BYTES>>>(w1, b1);
    k_moe2<<<dim3(HDIM/128, NSLOT/128, NEXP), 256, G32_SMEM_BYTES>>>(w2, b2);
    k_combine<<<NTOK, 256>>>(mom, ln2g, ln2b, out);
}